// round 9
// baseline (speedup 1.0000x reference)
#include <cuda_runtime.h>
#include <cstdint>

#define Hh 51
#define Lt 999
#define NB 16
#define NCTA 128
#define THREADS 512
#define WARPS 16
#define NTW 2          // n8-tiles per warp (32 tiles total)
#define NC1 7          // K-chunks layer1 (K=56: h1[51] + x + pad)
#define NC2 14         // K-chunks layer2 (K=112)
#define XCHP 65
#define RSTRIDE (2*NC1*128)   // per-region floats (hi+lo planes)

// shared memory float offsets
#define OFF_B1PK 0
#define SZ_B1PK (32*NC1*64)              // 14336
#define OFF_B2PK (OFF_B1PK + SZ_B1PK)
#define SZ_B2PK (32*NC2*64)              // 28672
#define OFF_HBUF (OFF_B2PK + SZ_B2PK)    // 4 regions: R0,R1 (h1+x), Q0,Q1 (h2)
#define SZ_HBUF (4*RSTRIDE)              // 7168
#define OFF_OCH  (OFF_HBUF + SZ_HBUF)
#define OFF_OP   (OFF_OCH + NB*XCHP)     // 2 x 256 double-buffered partials
#define OFF_BS1  (OFF_OP + 2*WARPS*NB)   // 4 x 64 exact biases L1
#define OFF_BS2  (OFF_BS1 + 4*64)
#define OFF_WL   (OFF_BS2 + 4*64)        // 64 (W_lin padded)
#define OFF_BLIN (OFF_WL + 64)
#define SMEM_FLOATS (OFF_BLIN + 4)

__device__ __forceinline__ uint32_t to_tf32(float x) {
    uint32_t u; asm("cvt.rna.tf32.f32 %0, %1;" : "=r"(u) : "f"(x)); return u;
}
__device__ __forceinline__ void mma8(float* d, uint4 a, uint2 b) {
    asm("mma.sync.aligned.m16n8k8.row.col.f32.tf32.tf32.f32 "
        "{%0,%1,%2,%3}, {%4,%5,%6,%7}, {%8,%9}, {%0,%1,%2,%3};"
        : "+f"(d[0]), "+f"(d[1]), "+f"(d[2]), "+f"(d[3])
        : "r"(a.x), "r"(a.y), "r"(a.z), "r"(a.w), "r"(b.x), "r"(b.y));
}
__device__ __forceinline__ float frcp(float x) {
    float r; asm("rcp.approx.f32 %0, %1;" : "=f"(r) : "f"(x)); return r;
}
__device__ __forceinline__ float fex2(float x) {
    float r; asm("ex2.approx.f32 %0, %1;" : "=f"(r) : "f"(x)); return r;
}
__device__ __forceinline__ float sigf(float x) {
    return frcp(fex2(-1.4426950408889634f * x) + 1.0f);
}
__device__ __forceinline__ float ftanh(float x) {
    return fmaf(-2.0f, frcp(fex2(2.8853901817779268f * x) + 1.0f), 1.0f);
}
// hbuf slot for value (batch b, unit u), plane 0=hi 1=lo
__device__ __forceinline__ int hidx(int region, int plane, int b, int u) {
    const int colin = u & 7, ch = u >> 3;
    const int tl = ((b & 7) << 2) + (colin & 3);
    const int reg = ((colin >= 4) ? 2 : 0) + ((b >= 8) ? 1 : 0);
    return region*RSTRIDE + plane*(NC1*128) + ch*128 + tl*4 + reg;
}

__global__ void __launch_bounds__(THREADS, 1)
lstm_kernel(const float* __restrict__ x,
            const float* __restrict__ gWih1, const float* __restrict__ gWhh1,
            const float* __restrict__ gbih1, const float* __restrict__ gbhh1,
            const float* __restrict__ gWih2, const float* __restrict__ gWhh2,
            const float* __restrict__ gbih2, const float* __restrict__ gbhh2,
            const float* __restrict__ gWlin, const float* __restrict__ gblin,
            float* __restrict__ out)
{
    extern __shared__ float sm[];
    float* b1pk = sm + OFF_B1PK;
    float* b2pk = sm + OFF_B2PK;
    float* hbuf = sm + OFF_HBUF;
    uint32_t* hbu = (uint32_t*)hbuf;
    float* och  = sm + OFF_OCH;
    float* opart= sm + OFF_OP;
    float* bsm1 = sm + OFF_BS1;
    float* bsm2 = sm + OFF_BS2;
    float* wlsm = sm + OFF_WL;

    const int tid  = threadIdx.x;
    const int wid  = tid >> 5;
    const int lane = tid & 31;
    const int gid  = lane >> 2, tq = lane & 3;
    const int bmy  = gid + ((tq & 1) << 3);   // this lane's batch
    const int uh   = tq >> 1;                 // unit half within tile
    const int b0   = blockIdx.x * NB;

    // ---- pack layer-1 weights (tf32, fragment order); bias column ZERO ----
    for (int idx = tid; idx < SZ_B1PK; idx += THREADS) {
        const int r   = idx & 1;
        const int ln  = (idx >> 1) & 31;
        const int c   = (idx >> 6) % NC1;
        const int tau = idx / (NC1 * 64);
        const int n = tau*8 + (ln >> 2);
        const int u = n >> 2, ty = n & 3;
        const int k = c*8 + (ln & 3) + 4*r;
        float v = 0.f;
        if (u < Hh) {
            const int R = ty*Hh + u;
            if (k < Hh)       v = gWhh1[R*Hh + k];
            else if (k == Hh) v = gWih1[R];          // x slot (unit 51)
        }
        b1pk[idx] = __uint_as_float(to_tf32(v));
    }
    // ---- pack layer-2 weights; x and bias columns ZERO ----
    for (int idx = tid; idx < SZ_B2PK; idx += THREADS) {
        const int r   = idx & 1;
        const int ln  = (idx >> 1) & 31;
        const int c   = (idx >> 6) % NC2;
        const int tau = idx / (NC2 * 64);
        const int n = tau*8 + (ln >> 2);
        const int u = n >> 2, ty = n & 3;
        const int k = c*8 + (ln & 3) + 4*r;
        float v = 0.f;
        if (u < Hh) {
            const int R = ty*Hh + u;
            if (k < Hh) v = gWih2[R*Hh + k];
            else if (k >= 56) { const int kq = k - 56; if (kq < Hh) v = gWhh2[R*Hh + kq]; }
        }
        b2pk[idx] = __uint_as_float(to_tf32(v));
    }
    for (int i = tid; i < SZ_HBUF; i += THREADS) hbuf[i] = 0.f;
    // exact biases / W_lin into smem (padded to 64 units with zeros)
    for (int i = tid; i < 4*64; i += THREADS) {
        const int ty = i >> 6, u = i & 63;
        const int R = ty*Hh + u;
        bsm1[i] = (u < Hh) ? (gbih1[R] + gbhh1[R]) : 0.f;
        bsm2[i] = (u < Hh) ? (gbih2[R] + gbhh2[R]) : 0.f;
    }
    if (tid < 64) wlsm[tid] = (tid < Hh) ? gWlin[tid] : 0.f;
    if (tid == 0) sm[OFF_BLIN] = gblin[0];
    __syncthreads();
    // x[0] into region 1 (prologue read region)
    if (tid < NB) {
        const float xv = x[(b0 + tid)*Lt + 0];
        const uint32_t hi = to_tf32(xv);
        hbu[hidx(1, 0, tid, 51)] = hi;
        hbu[hidx(1, 1, tid, 51)] = to_tf32(xv - __uint_as_float(hi));
    }
    __syncthreads();

    // ---- hoist B fragments into registers (loop-invariant) ----
    uint2 B1f[NTW][NC1], B2f[NTW][NC2];
    #pragma unroll
    for (int j = 0; j < NTW; j++) {
        const int tau = wid + 16*j;
        #pragma unroll
        for (int c = 0; c < NC1; c++)
            B1f[j][c] = *(const uint2*)&b1pk[((tau*NC1 + c)*32 + lane)*2];
        #pragma unroll
        for (int c = 0; c < NC2; c++)
            B2f[j][c] = *(const uint2*)&b2pk[((tau*NC2 + c)*32 + lane)*2];
    }
    float cst1[NTW] = {0.f,0.f}, cst2[NTW] = {0.f,0.f};

    // ================= prologue: h1[0] = cell1(x[0], 0) =================
    {
        float xf = 0.f;
        if (tid < NB) xf = x[(b0 + tid)*Lt + 1];
        float a1[NTW][4];
        #pragma unroll
        for (int j = 0; j < NTW; j++) { a1[j][0]=a1[j][1]=a1[j][2]=a1[j][3]=0.f; }
        #pragma unroll
        for (int c = 0; c < NC1; c++) {
            const uint4 ah = *(const uint4*)&hbuf[1*RSTRIDE + c*128 + lane*4];
            const uint4 al = *(const uint4*)&hbuf[1*RSTRIDE + NC1*128 + c*128 + lane*4];
            #pragma unroll
            for (int j = 0; j < NTW; j++) {
                mma8(a1[j], ah, B1f[j][c]);
                mma8(a1[j], al, B1f[j][c]);
            }
        }
        #pragma unroll
        for (int j = 0; j < NTW; j++) {
            const int u = 2*(wid + 16*j) + uh;
            const float sA = (tq & 1) ? a1[j][0] : a1[j][2];
            const float sB = (tq & 1) ? a1[j][1] : a1[j][3];
            const float rA = __shfl_xor_sync(0xffffffffu, sA, 1);
            const float rB = __shfl_xor_sync(0xffffffffu, sB, 1);
            float gi, gf, gg, go;
            if (tq & 1) { gi = rA; gf = rB; gg = a1[j][2]; go = a1[j][3]; }
            else        { gi = a1[j][0]; gf = a1[j][1]; gg = rA; go = rB; }
            const float cn = fmaf(sigf(gf + bsm1[64 + u]), cst1[j],
                                  sigf(gi + bsm1[u]) * ftanh(gg + bsm1[128 + u]));
            cst1[j] = cn;
            const float hn = sigf(go + bsm1[192 + u]) * ftanh(cn);
            if (u < Hh) {
                const uint32_t hi = to_tf32(hn);
                hbu[hidx(0, 0, bmy, u)] = hi;
                hbu[hidx(0, 1, bmy, u)] = to_tf32(hn - __uint_as_float(hi));
            }
        }
        if (tid < NB) {
            const uint32_t hi = to_tf32(xf);
            hbu[hidx(0, 0, tid, 51)] = hi;
            hbu[hidx(0, 1, tid, 51)] = to_tf32(xf - __uint_as_float(hi));
        }
        __syncthreads();
    }

    // ================= main loop: step n does L1[n+1] + L2[n] =================
    for (int n = 0; n < Lt; ++n) {
        const int rr = n & 1, wr = 1 - rr;       // R (h1+x) regions
        const int qr = 2 + rr, qw = 3 - rr;      // Q (h2) regions

        float xf = 0.f;
        const bool havex = (tid < NB) && (n + 2 < Lt);
        if (havex) xf = x[(b0 + tid)*Lt + n + 2];

        float a1[NTW][4], a2[NTW][4];
        #pragma unroll
        for (int j = 0; j < NTW; j++) {
            a1[j][0]=a1[j][1]=a1[j][2]=a1[j][3]=0.f;
            a2[j][0]=a2[j][1]=a2[j][2]=a2[j][3]=0.f;
        }
        // h1[n] (+x[n+1]) chunks feed BOTH layers
        #pragma unroll
        for (int c = 0; c < NC1; c++) {
            const uint4 ah = *(const uint4*)&hbuf[rr*RSTRIDE + c*128 + lane*4];
            const uint4 al = *(const uint4*)&hbuf[rr*RSTRIDE + NC1*128 + c*128 + lane*4];
            #pragma unroll
            for (int j = 0; j < NTW; j++) {
                mma8(a1[j], ah, B1f[j][c]);
                mma8(a1[j], al, B1f[j][c]);
                mma8(a2[j], ah, B2f[j][c]);
                mma8(a2[j], al, B2f[j][c]);
            }
        }
        // h2[n-1] chunks feed layer-2 only
        #pragma unroll
        for (int c = NC1; c < NC2; c++) {
            const int cc = c - NC1;
            const uint4 ah = *(const uint4*)&hbuf[qr*RSTRIDE + cc*128 + lane*4];
            const uint4 al = *(const uint4*)&hbuf[qr*RSTRIDE + NC1*128 + cc*128 + lane*4];
            #pragma unroll
            for (int j = 0; j < NTW; j++) {
                mma8(a2[j], ah, B2f[j][c]);
                mma8(a2[j], al, B2f[j][c]);
            }
        }

        // ---- epilogue: L1 -> h1[n+1] into wr ----
        #pragma unroll
        for (int j = 0; j < NTW; j++) {
            const int u = 2*(wid + 16*j) + uh;
            const float sA = (tq & 1) ? a1[j][0] : a1[j][2];
            const float sB = (tq & 1) ? a1[j][1] : a1[j][3];
            const float rA = __shfl_xor_sync(0xffffffffu, sA, 1);
            const float rB = __shfl_xor_sync(0xffffffffu, sB, 1);
            float gi, gf, gg, go;
            if (tq & 1) { gi = rA; gf = rB; gg = a1[j][2]; go = a1[j][3]; }
            else        { gi = a1[j][0]; gf = a1[j][1]; gg = rA; go = rB; }
            const float cn = fmaf(sigf(gf + bsm1[64 + u]), cst1[j],
                                  sigf(gi + bsm1[u]) * ftanh(gg + bsm1[128 + u]));
            cst1[j] = cn;
            const float hn = sigf(go + bsm1[192 + u]) * ftanh(cn);
            if (u < Hh) {
                const uint32_t hi = to_tf32(hn);
                hbu[hidx(wr, 0, bmy, u)] = hi;
                hbu[hidx(wr, 1, bmy, u)] = to_tf32(hn - __uint_as_float(hi));
            }
        }
        // ---- epilogue: L2 -> h2[n] into qw, output partial ----
        float ypart = 0.f;
        #pragma unroll
        for (int j = 0; j < NTW; j++) {
            const int u = 2*(wid + 16*j) + uh;
            const float sA = (tq & 1) ? a2[j][0] : a2[j][2];
            const float sB = (tq & 1) ? a2[j][1] : a2[j][3];
            const float rA = __shfl_xor_sync(0xffffffffu, sA, 1);
            const float rB = __shfl_xor_sync(0xffffffffu, sB, 1);
            float gi, gf, gg, go;
            if (tq & 1) { gi = rA; gf = rB; gg = a2[j][2]; go = a2[j][3]; }
            else        { gi = a2[j][0]; gf = a2[j][1]; gg = rA; go = rB; }
            const float cn = fmaf(sigf(gf + bsm2[64 + u]), cst2[j],
                                  sigf(gi + bsm2[u]) * ftanh(gg + bsm2[128 + u]));
            cst2[j] = cn;
            const float hn = sigf(go + bsm2[192 + u]) * ftanh(cn);
            if (u < Hh) {
                const uint32_t hi = to_tf32(hn);
                hbu[hidx(qw, 0, bmy, u)] = hi;
                hbu[hidx(qw, 1, bmy, u)] = to_tf32(hn - __uint_as_float(hi));
            }
            ypart = fmaf(hn, wlsm[u], ypart);
        }
        if (havex) {
            const uint32_t hi = to_tf32(xf);
            hbu[hidx(wr, 0, tid, 51)] = hi;
            hbu[hidx(wr, 1, tid, 51)] = to_tf32(xf - __uint_as_float(hi));
        }
        const float ys = ypart + __shfl_xor_sync(0xffffffffu, ypart, 2);
        if (tq < 2) opart[(n & 1)*(WARPS*NB) + wid*NB + ((tq & 1) << 3) + gid] = ys;
        __syncthreads();   // one barrier per step

        if (tid < NB) {
            float s = sm[OFF_BLIN];
            #pragma unroll
            for (int w8 = 0; w8 < WARPS; w8++)
                s += opart[(n & 1)*(WARPS*NB) + w8*NB + tid];
            och[tid*XCHP + (n & 63)] = s;
        }

        // ---- flush output chunk (coalesced) ----
        if ((n & 63) == 63 || n == Lt-1) {
            __syncthreads();
            const int t0c = n & ~63;
            const int wd = (n & 63) + 1;
            for (int i = tid; i < NB*wd; i += THREADS) {
                const int row = i / wd, col = i - row*wd;
                out[(b0+row)*Lt + t0c + col] = och[row*XCHP + col];
            }
        }
    }
}

extern "C" void kernel_launch(void* const* d_in, const int* in_sizes, int n_in,
                              void* d_out, int out_size)
{
    const float* x     = (const float*)d_in[0];
    const float* wih1  = (const float*)d_in[1];
    const float* whh1  = (const float*)d_in[2];
    const float* bih1  = (const float*)d_in[3];
    const float* bhh1  = (const float*)d_in[4];
    const float* wih2  = (const float*)d_in[5];
    const float* whh2  = (const float*)d_in[6];
    const float* bih2  = (const float*)d_in[7];
    const float* bhh2  = (const float*)d_in[8];
    const float* wlin  = (const float*)d_in[9];
    const float* blin  = (const float*)d_in[10];
    float* out = (float*)d_out;

    const size_t smem = (size_t)SMEM_FLOATS * sizeof(float);
    cudaFuncSetAttribute(lstm_kernel, cudaFuncAttributeMaxDynamicSharedMemorySize, (int)smem);
    lstm_kernel<<<NCTA, THREADS, smem>>>(x, wih1, whh1, bih1, bhh1,
                                         wih2, whh2, bih2, bhh2,
                                         wlin, blin, out);
}

// round 10
// speedup vs baseline: 1.0030x; 1.0030x over previous
#include <cuda_runtime.h>
#include <cstdint>

#define Hh 51
#define Lt 999
#define NB 16
#define NCTA 128
#define THREADS 512
#define WARPS 16
#define NTW 2          // n8-tiles per warp (32 tiles total)
#define NC1 7          // K-chunks layer1 (K=56: h1[51] + x + pad)
#define NC2 14         // K-chunks layer2 (K=112)
#define XCHP 65
#define RSTRIDE (2*NC1*128)   // per-region floats (hi+lo planes)

// shared memory float offsets
#define OFF_B1PK 0
#define SZ_B1PK (32*NC1*64)              // 14336
#define OFF_B2PK (OFF_B1PK + SZ_B1PK)
#define SZ_B2PK (32*NC2*64)              // 28672
#define OFF_HBUF (OFF_B2PK + SZ_B2PK)    // 4 regions: R0,R1 (h1+x), Q0,Q1 (h2)
#define SZ_HBUF (4*RSTRIDE)              // 7168
#define OFF_OCH  (OFF_HBUF + SZ_HBUF)
#define OFF_OP   (OFF_OCH + NB*XCHP)     // 2 x 256 double-buffered partials
#define OFF_BS1  (OFF_OP + 2*WARPS*NB)   // 4 x 64 exact biases L1
#define OFF_BS2  (OFF_BS1 + 4*64)
#define OFF_WL   (OFF_BS2 + 4*64)        // 64 (W_lin padded)
#define OFF_BLIN (OFF_WL + 64)
#define SMEM_FLOATS (OFF_BLIN + 4)

__device__ __forceinline__ uint32_t to_tf32(float x) {
    uint32_t u; asm("cvt.rna.tf32.f32 %0, %1;" : "=r"(u) : "f"(x)); return u;
}
__device__ __forceinline__ void mma8(float* d, uint4 a, uint2 b) {
    asm("mma.sync.aligned.m16n8k8.row.col.f32.tf32.tf32.f32 "
        "{%0,%1,%2,%3}, {%4,%5,%6,%7}, {%8,%9}, {%0,%1,%2,%3};"
        : "+f"(d[0]), "+f"(d[1]), "+f"(d[2]), "+f"(d[3])
        : "r"(a.x), "r"(a.y), "r"(a.z), "r"(a.w), "r"(b.x), "r"(b.y));
}
__device__ __forceinline__ float frcp(float x) {
    float r; asm("rcp.approx.f32 %0, %1;" : "=f"(r) : "f"(x)); return r;
}
__device__ __forceinline__ float fex2(float x) {
    float r; asm("ex2.approx.f32 %0, %1;" : "=f"(r) : "f"(x)); return r;
}
__device__ __forceinline__ float sigf(float x) {
    return frcp(fex2(-1.4426950408889634f * x) + 1.0f);
}
__device__ __forceinline__ float ftanh(float x) {
    return fmaf(-2.0f, frcp(fex2(2.8853901817779268f * x) + 1.0f), 1.0f);
}
// hbuf slot for value (batch b, unit u), plane 0=hi 1=lo
__device__ __forceinline__ int hidx(int region, int plane, int b, int u) {
    const int colin = u & 7, ch = u >> 3;
    const int tl = ((b & 7) << 2) + (colin & 3);
    const int reg = ((colin >= 4) ? 2 : 0) + ((b >= 8) ? 1 : 0);
    return region*RSTRIDE + plane*(NC1*128) + ch*128 + tl*4 + reg;
}

__global__ void __launch_bounds__(THREADS, 1)
lstm_kernel(const float* __restrict__ x,
            const float* __restrict__ gWih1, const float* __restrict__ gWhh1,
            const float* __restrict__ gbih1, const float* __restrict__ gbhh1,
            const float* __restrict__ gWih2, const float* __restrict__ gWhh2,
            const float* __restrict__ gbih2, const float* __restrict__ gbhh2,
            const float* __restrict__ gWlin, const float* __restrict__ gblin,
            float* __restrict__ out)
{
    extern __shared__ float sm[];
    float* b1pk = sm + OFF_B1PK;
    float* b2pk = sm + OFF_B2PK;
    float* hbuf = sm + OFF_HBUF;
    uint32_t* hbu = (uint32_t*)hbuf;
    float* och  = sm + OFF_OCH;
    float* opart= sm + OFF_OP;
    float* bsm1 = sm + OFF_BS1;
    float* bsm2 = sm + OFF_BS2;
    float* wlsm = sm + OFF_WL;

    const int tid  = threadIdx.x;
    const int wid  = tid >> 5;
    const int lane = tid & 31;
    const int gid  = lane >> 2, tq = lane & 3;
    const int bmy  = gid + ((tq & 1) << 3);   // this lane's batch
    const int uh   = tq >> 1;                 // unit half within tile
    const int b0   = blockIdx.x * NB;

    // ---- pack layer-1 weights (tf32, fragment order); bias column ZERO ----
    for (int idx = tid; idx < SZ_B1PK; idx += THREADS) {
        const int r   = idx & 1;
        const int ln  = (idx >> 1) & 31;
        const int c   = (idx >> 6) % NC1;
        const int tau = idx / (NC1 * 64);
        const int n = tau*8 + (ln >> 2);
        const int u = n >> 2, ty = n & 3;
        const int k = c*8 + (ln & 3) + 4*r;
        float v = 0.f;
        if (u < Hh) {
            const int R = ty*Hh + u;
            if (k < Hh)       v = gWhh1[R*Hh + k];
            else if (k == Hh) v = gWih1[R];          // x slot (unit 51)
        }
        b1pk[idx] = __uint_as_float(to_tf32(v));
    }
    // ---- pack layer-2 weights; x and bias columns ZERO ----
    for (int idx = tid; idx < SZ_B2PK; idx += THREADS) {
        const int r   = idx & 1;
        const int ln  = (idx >> 1) & 31;
        const int c   = (idx >> 6) % NC2;
        const int tau = idx / (NC2 * 64);
        const int n = tau*8 + (ln >> 2);
        const int u = n >> 2, ty = n & 3;
        const int k = c*8 + (ln & 3) + 4*r;
        float v = 0.f;
        if (u < Hh) {
            const int R = ty*Hh + u;
            if (k < Hh) v = gWih2[R*Hh + k];
            else if (k >= 56) { const int kq = k - 56; if (kq < Hh) v = gWhh2[R*Hh + kq]; }
        }
        b2pk[idx] = __uint_as_float(to_tf32(v));
    }
    for (int i = tid; i < SZ_HBUF; i += THREADS) hbuf[i] = 0.f;
    // exact biases / W_lin into smem (padded to 64 units with zeros)
    for (int i = tid; i < 4*64; i += THREADS) {
        const int ty = i >> 6, u = i & 63;
        const int R = ty*Hh + u;
        bsm1[i] = (u < Hh) ? (gbih1[R] + gbhh1[R]) : 0.f;
        bsm2[i] = (u < Hh) ? (gbih2[R] + gbhh2[R]) : 0.f;
    }
    if (tid < 64) wlsm[tid] = (tid < Hh) ? gWlin[tid] : 0.f;
    if (tid == 0) sm[OFF_BLIN] = gblin[0];
    __syncthreads();
    // x[0] into region 1 (prologue read region)
    if (tid < NB) {
        const float xv = x[(b0 + tid)*Lt + 0];
        const uint32_t hi = to_tf32(xv);
        hbu[hidx(1, 0, tid, 51)] = hi;
        hbu[hidx(1, 1, tid, 51)] = to_tf32(xv - __uint_as_float(hi));
    }
    __syncthreads();

    // ---- hoist B fragments into registers (loop-invariant) ----
    uint2 B1f[NTW][NC1], B2f[NTW][NC2];
    #pragma unroll
    for (int j = 0; j < NTW; j++) {
        const int tau = wid + 16*j;
        #pragma unroll
        for (int c = 0; c < NC1; c++)
            B1f[j][c] = *(const uint2*)&b1pk[((tau*NC1 + c)*32 + lane)*2];
        #pragma unroll
        for (int c = 0; c < NC2; c++)
            B2f[j][c] = *(const uint2*)&b2pk[((tau*NC2 + c)*32 + lane)*2];
    }
    float cst1[NTW] = {0.f,0.f}, cst2[NTW] = {0.f,0.f};

    // ================= prologue: h1[0] = cell1(x[0], 0) =================
    {
        float xf = 0.f;
        if (tid < NB) xf = x[(b0 + tid)*Lt + 1];
        float a1[NTW][4];
        #pragma unroll
        for (int j = 0; j < NTW; j++) { a1[j][0]=a1[j][1]=a1[j][2]=a1[j][3]=0.f; }
        #pragma unroll
        for (int c = 0; c < NC1; c++) {
            const uint4 ah = *(const uint4*)&hbuf[1*RSTRIDE + c*128 + lane*4];
            const uint4 al = *(const uint4*)&hbuf[1*RSTRIDE + NC1*128 + c*128 + lane*4];
            #pragma unroll
            for (int j = 0; j < NTW; j++) {
                mma8(a1[j], ah, B1f[j][c]);
                mma8(a1[j], al, B1f[j][c]);
            }
        }
        #pragma unroll
        for (int j = 0; j < NTW; j++) {
            const int u = 2*(wid + 16*j) + uh;
            const float sA = (tq & 1) ? a1[j][0] : a1[j][2];
            const float sB = (tq & 1) ? a1[j][1] : a1[j][3];
            const float rA = __shfl_xor_sync(0xffffffffu, sA, 1);
            const float rB = __shfl_xor_sync(0xffffffffu, sB, 1);
            float gi, gf, gg, go;
            if (tq & 1) { gi = rA; gf = rB; gg = a1[j][2]; go = a1[j][3]; }
            else        { gi = a1[j][0]; gf = a1[j][1]; gg = rA; go = rB; }
            const float cn = fmaf(sigf(gf + bsm1[64 + u]), cst1[j],
                                  sigf(gi + bsm1[u]) * ftanh(gg + bsm1[128 + u]));
            cst1[j] = cn;
            const float hn = sigf(go + bsm1[192 + u]) * ftanh(cn);
            if (u < Hh) {
                const uint32_t hi = to_tf32(hn);
                hbu[hidx(0, 0, bmy, u)] = hi;
                hbu[hidx(0, 1, bmy, u)] = to_tf32(hn - __uint_as_float(hi));
            }
        }
        if (tid < NB) {
            const uint32_t hi = to_tf32(xf);
            hbu[hidx(0, 0, tid, 51)] = hi;
            hbu[hidx(0, 1, tid, 51)] = to_tf32(xf - __uint_as_float(hi));
        }
        __syncthreads();
    }

    // ================= main loop: step n does L1[n+1] + L2[n] =================
    for (int n = 0; n < Lt; ++n) {
        const int rr = n & 1, wr = 1 - rr;       // R (h1+x) regions
        const int qr = 2 + rr, qw = 3 - rr;      // Q (h2) regions

        float xf = 0.f;
        const bool havex = (tid < NB) && (n + 2 < Lt);
        if (havex) xf = x[(b0 + tid)*Lt + n + 2];

        float a1[NTW][4], a2[NTW][4];
        #pragma unroll
        for (int j = 0; j < NTW; j++) {
            a1[j][0]=a1[j][1]=a1[j][2]=a1[j][3]=0.f;
            a2[j][0]=a2[j][1]=a2[j][2]=a2[j][3]=0.f;
        }
        // h1[n] (+x[n+1]) chunks feed BOTH layers
        #pragma unroll
        for (int c = 0; c < NC1; c++) {
            const uint4 ah = *(const uint4*)&hbuf[rr*RSTRIDE + c*128 + lane*4];
            const uint4 al = *(const uint4*)&hbuf[rr*RSTRIDE + NC1*128 + c*128 + lane*4];
            #pragma unroll
            for (int j = 0; j < NTW; j++) {
                mma8(a1[j], ah, B1f[j][c]);
                mma8(a1[j], al, B1f[j][c]);
                mma8(a2[j], ah, B2f[j][c]);
                mma8(a2[j], al, B2f[j][c]);
            }
        }
        // h2[n-1] chunks feed layer-2 only
        #pragma unroll
        for (int c = NC1; c < NC2; c++) {
            const int cc = c - NC1;
            const uint4 ah = *(const uint4*)&hbuf[qr*RSTRIDE + cc*128 + lane*4];
            const uint4 al = *(const uint4*)&hbuf[qr*RSTRIDE + NC1*128 + cc*128 + lane*4];
            #pragma unroll
            for (int j = 0; j < NTW; j++) {
                mma8(a2[j], ah, B2f[j][c]);
                mma8(a2[j], al, B2f[j][c]);
            }
        }

        // ---- epilogue: L1 -> h1[n+1] into wr ----
        #pragma unroll
        for (int j = 0; j < NTW; j++) {
            const int u = 2*(wid + 16*j) + uh;
            const float sA = (tq & 1) ? a1[j][0] : a1[j][2];
            const float sB = (tq & 1) ? a1[j][1] : a1[j][3];
            const float rA = __shfl_xor_sync(0xffffffffu, sA, 1);
            const float rB = __shfl_xor_sync(0xffffffffu, sB, 1);
            float gi, gf, gg, go;
            if (tq & 1) { gi = rA; gf = rB; gg = a1[j][2]; go = a1[j][3]; }
            else        { gi = a1[j][0]; gf = a1[j][1]; gg = rA; go = rB; }
            const float cn = fmaf(sigf(gf + bsm1[64 + u]), cst1[j],
                                  sigf(gi + bsm1[u]) * ftanh(gg + bsm1[128 + u]));
            cst1[j] = cn;
            const float hn = sigf(go + bsm1[192 + u]) * ftanh(cn);
            if (u < Hh) {
                const uint32_t hi = to_tf32(hn);
                hbu[hidx(wr, 0, bmy, u)] = hi;
                hbu[hidx(wr, 1, bmy, u)] = to_tf32(hn - __uint_as_float(hi));
            }
        }
        // ---- epilogue: L2 -> h2[n] into qw, output partial ----
        float ypart = 0.f;
        #pragma unroll
        for (int j = 0; j < NTW; j++) {
            const int u = 2*(wid + 16*j) + uh;
            const float sA = (tq & 1) ? a2[j][0] : a2[j][2];
            const float sB = (tq & 1) ? a2[j][1] : a2[j][3];
            const float rA = __shfl_xor_sync(0xffffffffu, sA, 1);
            const float rB = __shfl_xor_sync(0xffffffffu, sB, 1);
            float gi, gf, gg, go;
            if (tq & 1) { gi = rA; gf = rB; gg = a2[j][2]; go = a2[j][3]; }
            else        { gi = a2[j][0]; gf = a2[j][1]; gg = rA; go = rB; }
            const float cn = fmaf(sigf(gf + bsm2[64 + u]), cst2[j],
                                  sigf(gi + bsm2[u]) * ftanh(gg + bsm2[128 + u]));
            cst2[j] = cn;
            const float hn = sigf(go + bsm2[192 + u]) * ftanh(cn);
            if (u < Hh) {
                const uint32_t hi = to_tf32(hn);
                hbu[hidx(qw, 0, bmy, u)] = hi;
                hbu[hidx(qw, 1, bmy, u)] = to_tf32(hn - __uint_as_float(hi));
            }
            ypart = fmaf(hn, wlsm[u], ypart);
        }
        if (havex) {
            const uint32_t hi = to_tf32(xf);
            hbu[hidx(wr, 0, tid, 51)] = hi;
            hbu[hidx(wr, 1, tid, 51)] = to_tf32(xf - __uint_as_float(hi));
        }
        const float ys = ypart + __shfl_xor_sync(0xffffffffu, ypart, 2);
        if (tq < 2) opart[(n & 1)*(WARPS*NB) + wid*NB + ((tq & 1) << 3) + gid] = ys;
        __syncthreads();   // one barrier per step

        if (tid < NB) {
            float s = sm[OFF_BLIN];
            #pragma unroll
            for (int w8 = 0; w8 < WARPS; w8++)
                s += opart[(n & 1)*(WARPS*NB) + w8*NB + tid];
            och[tid*XCHP + (n & 63)] = s;
        }

        // ---- flush output chunk (coalesced) ----
        if ((n & 63) == 63 || n == Lt-1) {
            __syncthreads();
            const int t0c = n & ~63;
            const int wd = (n & 63) + 1;
            for (int i = tid; i < NB*wd; i += THREADS) {
                const int row = i / wd, col = i - row*wd;
                out[(b0+row)*Lt + t0c + col] = och[row*XCHP + col];
            }
        }
    }
}

extern "C" void kernel_launch(void* const* d_in, const int* in_sizes, int n_in,
                              void* d_out, int out_size)
{
    const float* x     = (const float*)d_in[0];
    const float* wih1  = (const float*)d_in[1];
    const float* whh1  = (const float*)d_in[2];
    const float* bih1  = (const float*)d_in[3];
    const float* bhh1  = (const float*)d_in[4];
    const float* wih2  = (const float*)d_in[5];
    const float* whh2  = (const float*)d_in[6];
    const float* bih2  = (const float*)d_in[7];
    const float* bhh2  = (const float*)d_in[8];
    const float* wlin  = (const float*)d_in[9];
    const float* blin  = (const float*)d_in[10];
    float* out = (float*)d_out;

    const size_t smem = (size_t)SMEM_FLOATS * sizeof(float);
    cudaFuncSetAttribute(lstm_kernel, cudaFuncAttributeMaxDynamicSharedMemorySize, (int)smem);
    lstm_kernel<<<NCTA, THREADS, smem>>>(x, wih1, whh1, bih1, bhh1,
                                         wih2, whh2, bih2, bhh2,
                                         wlin, blin, out);
}

// round 11
// speedup vs baseline: 1.0033x; 1.0003x over previous
#include <cuda_runtime.h>
#include <cstdint>

#define Hh 51
#define Lt 999
#define NB 16
#define NCTA 128
#define THREADS 512
#define WARPS 16
#define NTW 2          // n8-tiles per warp (32 tiles total)
#define NC1 7          // K-chunks layer1 (K=56: h1[51] + x + pad)
#define NC2 14         // K-chunks layer2 (K=112)
#define XCHP 65
#define RSTRIDE (2*NC1*128)   // per-region floats (hi+lo planes)

// shared memory float offsets
#define OFF_B1PK 0
#define SZ_B1PK (32*NC1*64)              // 14336
#define OFF_B2PK (OFF_B1PK + SZ_B1PK)
#define SZ_B2PK (32*NC2*64)              // 28672
#define OFF_HBUF (OFF_B2PK + SZ_B2PK)    // 4 regions: R0,R1 (h1+x), Q0,Q1 (h2)
#define SZ_HBUF (4*RSTRIDE)              // 7168
#define OFF_OCH  (OFF_HBUF + SZ_HBUF)
#define OFF_OP   (OFF_OCH + NB*XCHP)     // 2 x 256 double-buffered partials
#define OFF_BS1  (OFF_OP + 2*WARPS*NB)   // 4 x 64 exact biases L1
#define OFF_BS2  (OFF_BS1 + 4*64)
#define OFF_WL   (OFF_BS2 + 4*64)        // 64 (W_lin padded)
#define OFF_BLIN (OFF_WL + 64)
#define SMEM_FLOATS (OFF_BLIN + 4)

__device__ __forceinline__ uint32_t to_tf32(float x) {
    uint32_t u; asm("cvt.rna.tf32.f32 %0, %1;" : "=r"(u) : "f"(x)); return u;
}
__device__ __forceinline__ void mma8(float* d, uint4 a, uint2 b) {
    asm("mma.sync.aligned.m16n8k8.row.col.f32.tf32.tf32.f32 "
        "{%0,%1,%2,%3}, {%4,%5,%6,%7}, {%8,%9}, {%0,%1,%2,%3};"
        : "+f"(d[0]), "+f"(d[1]), "+f"(d[2]), "+f"(d[3])
        : "r"(a.x), "r"(a.y), "r"(a.z), "r"(a.w), "r"(b.x), "r"(b.y));
}
__device__ __forceinline__ float frcp(float x) {
    float r; asm("rcp.approx.f32 %0, %1;" : "=f"(r) : "f"(x)); return r;
}
__device__ __forceinline__ float fex2(float x) {
    float r; asm("ex2.approx.f32 %0, %1;" : "=f"(r) : "f"(x)); return r;
}
__device__ __forceinline__ float sigf(float x) {
    return frcp(fex2(-1.4426950408889634f * x) + 1.0f);
}
__device__ __forceinline__ float ftanh(float x) {
    return fmaf(-2.0f, frcp(fex2(2.8853901817779268f * x) + 1.0f), 1.0f);
}
// hbuf slot for value (batch b, unit u), plane 0=hi 1=lo
__device__ __forceinline__ int hidx(int region, int plane, int b, int u) {
    const int colin = u & 7, ch = u >> 3;
    const int tl = ((b & 7) << 2) + (colin & 3);
    const int reg = ((colin >= 4) ? 2 : 0) + ((b >= 8) ? 1 : 0);
    return region*RSTRIDE + plane*(NC1*128) + ch*128 + tl*4 + reg;
}

__global__ void __launch_bounds__(THREADS, 1)
lstm_kernel(const float* __restrict__ x,
            const float* __restrict__ gWih1, const float* __restrict__ gWhh1,
            const float* __restrict__ gbih1, const float* __restrict__ gbhh1,
            const float* __restrict__ gWih2, const float* __restrict__ gWhh2,
            const float* __restrict__ gbih2, const float* __restrict__ gbhh2,
            const float* __restrict__ gWlin, const float* __restrict__ gblin,
            float* __restrict__ out)
{
    extern __shared__ float sm[];
    float* b1pk = sm + OFF_B1PK;
    float* b2pk = sm + OFF_B2PK;
    float* hbuf = sm + OFF_HBUF;
    uint32_t* hbu = (uint32_t*)hbuf;
    float* och  = sm + OFF_OCH;
    float* opart= sm + OFF_OP;
    float* bsm1 = sm + OFF_BS1;
    float* bsm2 = sm + OFF_BS2;
    float* wlsm = sm + OFF_WL;

    const int tid  = threadIdx.x;
    const int wid  = tid >> 5;
    const int lane = tid & 31;
    const int gid  = lane >> 2, tq = lane & 3;
    const int bmy  = gid + ((tq & 1) << 3);   // this lane's batch
    const int uh   = tq >> 1;                 // unit half within tile
    const int b0   = blockIdx.x * NB;

    // ---- pack layer-1 weights (tf32, fragment order); bias column ZERO ----
    for (int idx = tid; idx < SZ_B1PK; idx += THREADS) {
        const int r   = idx & 1;
        const int ln  = (idx >> 1) & 31;
        const int c   = (idx >> 6) % NC1;
        const int tau = idx / (NC1 * 64);
        const int n = tau*8 + (ln >> 2);
        const int u = n >> 2, ty = n & 3;
        const int k = c*8 + (ln & 3) + 4*r;
        float v = 0.f;
        if (u < Hh) {
            const int R = ty*Hh + u;
            if (k < Hh)       v = gWhh1[R*Hh + k];
            else if (k == Hh) v = gWih1[R];          // x slot (unit 51)
        }
        b1pk[idx] = __uint_as_float(to_tf32(v));
    }
    // ---- pack layer-2 weights; x and bias columns ZERO ----
    for (int idx = tid; idx < SZ_B2PK; idx += THREADS) {
        const int r   = idx & 1;
        const int ln  = (idx >> 1) & 31;
        const int c   = (idx >> 6) % NC2;
        const int tau = idx / (NC2 * 64);
        const int n = tau*8 + (ln >> 2);
        const int u = n >> 2, ty = n & 3;
        const int k = c*8 + (ln & 3) + 4*r;
        float v = 0.f;
        if (u < Hh) {
            const int R = ty*Hh + u;
            if (k < Hh) v = gWih2[R*Hh + k];
            else if (k >= 56) { const int kq = k - 56; if (kq < Hh) v = gWhh2[R*Hh + kq]; }
        }
        b2pk[idx] = __uint_as_float(to_tf32(v));
    }
    for (int i = tid; i < SZ_HBUF; i += THREADS) hbuf[i] = 0.f;
    // exact biases / W_lin into smem (padded to 64 units with zeros)
    for (int i = tid; i < 4*64; i += THREADS) {
        const int ty = i >> 6, u = i & 63;
        const int R = ty*Hh + u;
        bsm1[i] = (u < Hh) ? (gbih1[R] + gbhh1[R]) : 0.f;
        bsm2[i] = (u < Hh) ? (gbih2[R] + gbhh2[R]) : 0.f;
    }
    if (tid < 64) wlsm[tid] = (tid < Hh) ? gWlin[tid] : 0.f;
    if (tid == 0) sm[OFF_BLIN] = gblin[0];
    __syncthreads();
    // x[0] into region 1 (prologue read region)
    if (tid < NB) {
        const float xv = x[(b0 + tid)*Lt + 0];
        const uint32_t hi = to_tf32(xv);
        hbu[hidx(1, 0, tid, 51)] = hi;
        hbu[hidx(1, 1, tid, 51)] = to_tf32(xv - __uint_as_float(hi));
    }
    __syncthreads();

    // ---- hoist B fragments into registers (loop-invariant) ----
    uint2 B1f[NTW][NC1], B2f[NTW][NC2];
    #pragma unroll
    for (int j = 0; j < NTW; j++) {
        const int tau = wid + 16*j;
        #pragma unroll
        for (int c = 0; c < NC1; c++)
            B1f[j][c] = *(const uint2*)&b1pk[((tau*NC1 + c)*32 + lane)*2];
        #pragma unroll
        for (int c = 0; c < NC2; c++)
            B2f[j][c] = *(const uint2*)&b2pk[((tau*NC2 + c)*32 + lane)*2];
    }
    float cst1[NTW] = {0.f,0.f}, cst2[NTW] = {0.f,0.f};

    // ================= prologue: h1[0] = cell1(x[0], 0) =================
    {
        float xf = 0.f;
        if (tid < NB) xf = x[(b0 + tid)*Lt + 1];
        float a1[NTW][4];
        #pragma unroll
        for (int j = 0; j < NTW; j++) { a1[j][0]=a1[j][1]=a1[j][2]=a1[j][3]=0.f; }
        #pragma unroll
        for (int c = 0; c < NC1; c++) {
            const uint4 ah = *(const uint4*)&hbuf[1*RSTRIDE + c*128 + lane*4];
            const uint4 al = *(const uint4*)&hbuf[1*RSTRIDE + NC1*128 + c*128 + lane*4];
            #pragma unroll
            for (int j = 0; j < NTW; j++) {
                mma8(a1[j], ah, B1f[j][c]);
                mma8(a1[j], al, B1f[j][c]);
            }
        }
        #pragma unroll
        for (int j = 0; j < NTW; j++) {
            const int u = 2*(wid + 16*j) + uh;
            const float sA = (tq & 1) ? a1[j][0] : a1[j][2];
            const float sB = (tq & 1) ? a1[j][1] : a1[j][3];
            const float rA = __shfl_xor_sync(0xffffffffu, sA, 1);
            const float rB = __shfl_xor_sync(0xffffffffu, sB, 1);
            float gi, gf, gg, go;
            if (tq & 1) { gi = rA; gf = rB; gg = a1[j][2]; go = a1[j][3]; }
            else        { gi = a1[j][0]; gf = a1[j][1]; gg = rA; go = rB; }
            const float cn = fmaf(sigf(gf + bsm1[64 + u]), cst1[j],
                                  sigf(gi + bsm1[u]) * ftanh(gg + bsm1[128 + u]));
            cst1[j] = cn;
            const float hn = sigf(go + bsm1[192 + u]) * ftanh(cn);
            if (u < Hh) {
                const uint32_t hi = to_tf32(hn);
                hbu[hidx(0, 0, bmy, u)] = hi;
                hbu[hidx(0, 1, bmy, u)] = to_tf32(hn - __uint_as_float(hi));
            }
        }
        if (tid < NB) {
            const uint32_t hi = to_tf32(xf);
            hbu[hidx(0, 0, tid, 51)] = hi;
            hbu[hidx(0, 1, tid, 51)] = to_tf32(xf - __uint_as_float(hi));
        }
        __syncthreads();
    }

    // ================= main loop: step n does L1[n+1] + L2[n] =================
    for (int n = 0; n < Lt; ++n) {
        const int rr = n & 1, wr = 1 - rr;       // R (h1+x) regions
        const int qr = 2 + rr, qw = 3 - rr;      // Q (h2) regions

        float xf = 0.f;
        const bool havex = (tid < NB) && (n + 2 < Lt);
        if (havex) xf = x[(b0 + tid)*Lt + n + 2];

        float a1[NTW][4], a2[NTW][4];
        #pragma unroll
        for (int j = 0; j < NTW; j++) {
            a1[j][0]=a1[j][1]=a1[j][2]=a1[j][3]=0.f;
            a2[j][0]=a2[j][1]=a2[j][2]=a2[j][3]=0.f;
        }
        // h1[n] (+x[n+1]) chunks feed BOTH layers
        #pragma unroll
        for (int c = 0; c < NC1; c++) {
            const uint4 ah = *(const uint4*)&hbuf[rr*RSTRIDE + c*128 + lane*4];
            const uint4 al = *(const uint4*)&hbuf[rr*RSTRIDE + NC1*128 + c*128 + lane*4];
            #pragma unroll
            for (int j = 0; j < NTW; j++) {
                mma8(a1[j], ah, B1f[j][c]);
                mma8(a1[j], al, B1f[j][c]);
                mma8(a2[j], ah, B2f[j][c]);
                mma8(a2[j], al, B2f[j][c]);
            }
        }
        // h2[n-1] chunks feed layer-2 only
        #pragma unroll
        for (int c = NC1; c < NC2; c++) {
            const int cc = c - NC1;
            const uint4 ah = *(const uint4*)&hbuf[qr*RSTRIDE + cc*128 + lane*4];
            const uint4 al = *(const uint4*)&hbuf[qr*RSTRIDE + NC1*128 + cc*128 + lane*4];
            #pragma unroll
            for (int j = 0; j < NTW; j++) {
                mma8(a2[j], ah, B2f[j][c]);
                mma8(a2[j], al, B2f[j][c]);
            }
        }

        // ---- epilogue: L1 -> h1[n+1] into wr ----
        #pragma unroll
        for (int j = 0; j < NTW; j++) {
            const int u = 2*(wid + 16*j) + uh;
            const float sA = (tq & 1) ? a1[j][0] : a1[j][2];
            const float sB = (tq & 1) ? a1[j][1] : a1[j][3];
            const float rA = __shfl_xor_sync(0xffffffffu, sA, 1);
            const float rB = __shfl_xor_sync(0xffffffffu, sB, 1);
            float gi, gf, gg, go;
            if (tq & 1) { gi = rA; gf = rB; gg = a1[j][2]; go = a1[j][3]; }
            else        { gi = a1[j][0]; gf = a1[j][1]; gg = rA; go = rB; }
            const float cn = fmaf(sigf(gf + bsm1[64 + u]), cst1[j],
                                  sigf(gi + bsm1[u]) * ftanh(gg + bsm1[128 + u]));
            cst1[j] = cn;
            const float hn = sigf(go + bsm1[192 + u]) * ftanh(cn);
            if (u < Hh) {
                const uint32_t hi = to_tf32(hn);
                hbu[hidx(wr, 0, bmy, u)] = hi;
                hbu[hidx(wr, 1, bmy, u)] = to_tf32(hn - __uint_as_float(hi));
            }
        }
        // ---- epilogue: L2 -> h2[n] into qw, output partial ----
        float ypart = 0.f;
        #pragma unroll
        for (int j = 0; j < NTW; j++) {
            const int u = 2*(wid + 16*j) + uh;
            const float sA = (tq & 1) ? a2[j][0] : a2[j][2];
            const float sB = (tq & 1) ? a2[j][1] : a2[j][3];
            const float rA = __shfl_xor_sync(0xffffffffu, sA, 1);
            const float rB = __shfl_xor_sync(0xffffffffu, sB, 1);
            float gi, gf, gg, go;
            if (tq & 1) { gi = rA; gf = rB; gg = a2[j][2]; go = a2[j][3]; }
            else        { gi = a2[j][0]; gf = a2[j][1]; gg = rA; go = rB; }
            const float cn = fmaf(sigf(gf + bsm2[64 + u]), cst2[j],
                                  sigf(gi + bsm2[u]) * ftanh(gg + bsm2[128 + u]));
            cst2[j] = cn;
            const float hn = sigf(go + bsm2[192 + u]) * ftanh(cn);
            if (u < Hh) {
                const uint32_t hi = to_tf32(hn);
                hbu[hidx(qw, 0, bmy, u)] = hi;
                hbu[hidx(qw, 1, bmy, u)] = to_tf32(hn - __uint_as_float(hi));
            }
            ypart = fmaf(hn, wlsm[u], ypart);
        }
        if (havex) {
            const uint32_t hi = to_tf32(xf);
            hbu[hidx(wr, 0, tid, 51)] = hi;
            hbu[hidx(wr, 1, tid, 51)] = to_tf32(xf - __uint_as_float(hi));
        }
        const float ys = ypart + __shfl_xor_sync(0xffffffffu, ypart, 2);
        if (tq < 2) opart[(n & 1)*(WARPS*NB) + wid*NB + ((tq & 1) << 3) + gid] = ys;
        __syncthreads();   // one barrier per step

        if (tid < NB) {
            float s = sm[OFF_BLIN];
            #pragma unroll
            for (int w8 = 0; w8 < WARPS; w8++)
                s += opart[(n & 1)*(WARPS*NB) + w8*NB + tid];
            och[tid*XCHP + (n & 63)] = s;
        }

        // ---- flush output chunk (coalesced) ----
        if ((n & 63) == 63 || n == Lt-1) {
            __syncthreads();
            const int t0c = n & ~63;
            const int wd = (n & 63) + 1;
            for (int i = tid; i < NB*wd; i += THREADS) {
                const int row = i / wd, col = i - row*wd;
                out[(b0+row)*Lt + t0c + col] = och[row*XCHP + col];
            }
        }
    }
}

extern "C" void kernel_launch(void* const* d_in, const int* in_sizes, int n_in,
                              void* d_out, int out_size)
{
    const float* x     = (const float*)d_in[0];
    const float* wih1  = (const float*)d_in[1];
    const float* whh1  = (const float*)d_in[2];
    const float* bih1  = (const float*)d_in[3];
    const float* bhh1  = (const float*)d_in[4];
    const float* wih2  = (const float*)d_in[5];
    const float* whh2  = (const float*)d_in[6];
    const float* bih2  = (const float*)d_in[7];
    const float* bhh2  = (const float*)d_in[8];
    const float* wlin  = (const float*)d_in[9];
    const float* blin  = (const float*)d_in[10];
    float* out = (float*)d_out;

    const size_t smem = (size_t)SMEM_FLOATS * sizeof(float);
    cudaFuncSetAttribute(lstm_kernel, cudaFuncAttributeMaxDynamicSharedMemorySize, (int)smem);
    lstm_kernel<<<NCTA, THREADS, smem>>>(x, wih1, whh1, bih1, bhh1,
                                         wih2, whh2, bih2, bhh2,
                                         wlin, blin, out);
}

// round 12
// speedup vs baseline: 1.1287x; 1.1250x over previous
#include <cuda_runtime.h>
#include <cstdint>

#define Hh 51
#define Lt 999
#define NB 16
#define NCTA 128
#define THREADS 256
#define WARPS 8
#define NTW 4          // n8-tiles per warp (32 tiles total)
#define NC1 7          // K-chunks layer1 (K=56: h1[51] + x + pad)
#define NC2 14         // K-chunks layer2
#define XCHP 65
#define RSTRIDE (2*NC1*128)   // per-region floats (hi+lo planes)

// shared memory float offsets
#define OFF_B1PK 0
#define SZ_B1PK (32*448)                 // 32 tiles x 7 chunks x 64 (pair-packed)
#define OFF_B2PK (OFF_B1PK + SZ_B1PK)
#define SZ_B2PK (32*896)                 // 32 tiles x 14 chunks x 64 (pair-packed, 2 sides)
#define OFF_HBUF (OFF_B2PK + SZ_B2PK)    // 4 regions: R0,R1 (h1+x), Q0,Q1 (h2)
#define SZ_HBUF (4*RSTRIDE)              // 7168
#define OFF_OCH  (OFF_HBUF + SZ_HBUF)
#define OFF_OP   (OFF_OCH + NB*XCHP)     // 2 x 128 double-buffered partials
#define OFF_BLIN (OFF_OP + 2*WARPS*NB)
#define SMEM_FLOATS (OFF_BLIN + 4)

__device__ __forceinline__ uint32_t to_tf32(float x) {
    uint32_t u; asm("cvt.rna.tf32.f32 %0, %1;" : "=r"(u) : "f"(x)); return u;
}
__device__ __forceinline__ void mma8(float* d, uint4 a, uint32_t b0, uint32_t b1) {
    asm("mma.sync.aligned.m16n8k8.row.col.f32.tf32.tf32.f32 "
        "{%0,%1,%2,%3}, {%4,%5,%6,%7}, {%8,%9}, {%0,%1,%2,%3};"
        : "+f"(d[0]), "+f"(d[1]), "+f"(d[2]), "+f"(d[3])
        : "r"(a.x), "r"(a.y), "r"(a.z), "r"(a.w), "r"(b0), "r"(b1));
}
__device__ __forceinline__ float tanhapx(float x) {
    float r; asm("tanh.approx.f32 %0, %1;" : "=f"(r) : "f"(x)); return r;
}
// hbuf slot for value (batch b, unit u), plane 0=hi 1=lo
__device__ __forceinline__ int hidx(int region, int plane, int b, int u) {
    const int colin = u & 7, ch = u >> 3;
    const int tl = ((b & 7) << 2) + (colin & 3);
    const int reg = ((colin >= 4) ? 2 : 0) + ((b >= 8) ? 1 : 0);
    return region*RSTRIDE + plane*(NC1*128) + ch*128 + tl*4 + reg;
}

__global__ void __launch_bounds__(THREADS, 1)
lstm_kernel(const float* __restrict__ x,
            const float* __restrict__ gWih1, const float* __restrict__ gWhh1,
            const float* __restrict__ gbih1, const float* __restrict__ gbhh1,
            const float* __restrict__ gWih2, const float* __restrict__ gWhh2,
            const float* __restrict__ gbih2, const float* __restrict__ gbhh2,
            const float* __restrict__ gWlin, const float* __restrict__ gblin,
            float* __restrict__ out)
{
    extern __shared__ float sm[];
    float* b1pk = sm + OFF_B1PK;
    float* b2pk = sm + OFF_B2PK;
    float* hbuf = sm + OFF_HBUF;
    uint32_t* hbu = (uint32_t*)hbuf;
    float* och  = sm + OFF_OCH;
    float* opart= sm + OFF_OP;

    const int tid  = threadIdx.x;
    const int wid  = tid >> 5;
    const int lane = tid & 31;
    const int gid  = lane >> 2, tq = lane & 3;
    const int bmy  = gid + ((tq & 1) << 3);   // this lane's batch
    const int uh   = tq >> 1;                 // unit half within tile
    const int b0   = blockIdx.x * NB;

    // ---- pack layer-1 weights, pair-friendly layout, tf32; bias col ZERO ----
    for (int idx = tid; idx < SZ_B1PK; idx += THREADS) {
        const int tau = idx / 448, rem = idx % 448;
        int c, ln, r;
        if (rem < 384) { const int p = rem >> 7, q = rem & 127;
            ln = q >> 2; const int w = q & 3; c = 2*p + (w >> 1); r = w & 1; }
        else { const int q = rem - 384; ln = q >> 1; r = q & 1; c = 6; }
        const int n = tau*8 + (ln >> 2);
        const int u = n >> 2, ty = n & 3;
        const int k = c*8 + (ln & 3) + 4*r;
        float v = 0.f;
        if (u < Hh) {
            const int R = ty*Hh + u;
            if (k < Hh)       v = gWhh1[R*Hh + k];
            else if (k == Hh) v = gWih1[R];          // x slot (unit 51)
        }
        b1pk[idx] = __uint_as_float(to_tf32(v));
    }
    // ---- pack layer-2 weights (two sides: h1-part, h2-part) ----
    for (int idx = tid; idx < SZ_B2PK; idx += THREADS) {
        const int tau = idx / 896, rem = idx % 896;
        const int side = rem / 448, rem2 = rem % 448;
        int c, ln, r;
        if (rem2 < 384) { const int p = rem2 >> 7, q = rem2 & 127;
            ln = q >> 2; const int w = q & 3; c = side*7 + 2*p + (w >> 1); r = w & 1; }
        else { const int q = rem2 - 384; ln = q >> 1; r = q & 1; c = side*7 + 6; }
        const int n = tau*8 + (ln >> 2);
        const int u = n >> 2, ty = n & 3;
        const int k = c*8 + (ln & 3) + 4*r;
        float v = 0.f;
        if (u < Hh) {
            const int R = ty*Hh + u;
            if (k < Hh) v = gWih2[R*Hh + k];
            else if (k >= 56) { const int kq = k - 56; if (kq < Hh) v = gWhh2[R*Hh + kq]; }
        }
        b2pk[idx] = __uint_as_float(to_tf32(v));
    }
    for (int i = tid; i < SZ_HBUF; i += THREADS) hbuf[i] = 0.f;
    if (tid == 0) sm[OFF_BLIN] = gblin[0];
    __syncthreads();
    // x[0] into region 1 (prologue read region)
    if (tid < NB) {
        const float xv = x[(b0 + tid)*Lt + 0];
        const uint32_t hi = to_tf32(xv);
        hbu[hidx(1, 0, tid, 51)] = hi;
        hbu[hidx(1, 1, tid, 51)] = to_tf32(xv - __uint_as_float(hi));
    }
    // per-lane exact biases: half-bias for i,f,o (sigmoid-via-tanh), full for g
    float wl[NTW], hb1[NTW][3], bg1[NTW], hb2[NTW][3], bg2[NTW];
    #pragma unroll
    for (int j = 0; j < NTW; j++) {
        const int u = 2*(wid + 8*j) + uh;
        const bool ok = (u < Hh);
        wl[j] = ok ? gWlin[u] : 0.f;
        hb1[j][0] = ok ? 0.5f*(gbih1[u] + gbhh1[u]) : 0.f;                   // i
        hb1[j][1] = ok ? 0.5f*(gbih1[Hh+u] + gbhh1[Hh+u]) : 0.f;            // f
        bg1[j]    = ok ? (gbih1[2*Hh+u] + gbhh1[2*Hh+u]) : 0.f;             // g
        hb1[j][2] = ok ? 0.5f*(gbih1[3*Hh+u] + gbhh1[3*Hh+u]) : 0.f;        // o
        hb2[j][0] = ok ? 0.5f*(gbih2[u] + gbhh2[u]) : 0.f;
        hb2[j][1] = ok ? 0.5f*(gbih2[Hh+u] + gbhh2[Hh+u]) : 0.f;
        bg2[j]    = ok ? (gbih2[2*Hh+u] + gbhh2[2*Hh+u]) : 0.f;
        hb2[j][2] = ok ? 0.5f*(gbih2[3*Hh+u] + gbhh2[3*Hh+u]) : 0.f;
    }
    float cst1[NTW] = {0.f,0.f,0.f,0.f}, cst2[NTW] = {0.f,0.f,0.f,0.f};
    __syncthreads();

    // ================= prologue: h1[0] = cell1(x[0], 0) =================
    {
        float xf = 0.f;
        if (tid < NB) xf = x[(b0 + tid)*Lt + 1];
        float a1[NTW][4];
        #pragma unroll
        for (int j = 0; j < NTW; j++) { a1[j][0]=a1[j][1]=a1[j][2]=a1[j][3]=0.f; }
        #pragma unroll
        for (int p = 0; p < 3; p++) {
            const float* ab = &hbuf[1*RSTRIDE + (2*p)*128 + lane*4];
            const uint4 ah0 = *(const uint4*)(ab);
            const uint4 ah1 = *(const uint4*)(ab + 128);
            const uint4 al0 = *(const uint4*)(ab + NC1*128);
            const uint4 al1 = *(const uint4*)(ab + NC1*128 + 128);
            #pragma unroll
            for (int j = 0; j < NTW; j++) {
                const int tau = wid + 8*j;
                const uint4 bv = *(const uint4*)&b1pk[tau*448 + p*128 + lane*4];
                mma8(a1[j], ah0, bv.x, bv.y);
                mma8(a1[j], al0, bv.x, bv.y);
                mma8(a1[j], ah1, bv.z, bv.w);
                mma8(a1[j], al1, bv.z, bv.w);
            }
        }
        {
            const uint4 ah = *(const uint4*)&hbuf[1*RSTRIDE + 6*128 + lane*4];
            const uint4 al = *(const uint4*)&hbuf[1*RSTRIDE + NC1*128 + 6*128 + lane*4];
            #pragma unroll
            for (int j = 0; j < NTW; j++) {
                const int tau = wid + 8*j;
                const uint2 bs = *(const uint2*)&b1pk[tau*448 + 384 + lane*2];
                mma8(a1[j], ah, bs.x, bs.y);
                mma8(a1[j], al, bs.x, bs.y);
            }
        }
        #pragma unroll
        for (int j = 0; j < NTW; j++) {
            const int u = 2*(wid + 8*j) + uh;
            const float sA = (tq & 1) ? a1[j][0] : a1[j][2];
            const float sB = (tq & 1) ? a1[j][1] : a1[j][3];
            const float rA = __shfl_xor_sync(0xffffffffu, sA, 1);
            const float rB = __shfl_xor_sync(0xffffffffu, sB, 1);
            float gi, gf, gg, go;
            if (tq & 1) { gi = rA; gf = rB; gg = a1[j][2]; go = a1[j][3]; }
            else        { gi = a1[j][0]; gf = a1[j][1]; gg = rA; go = rB; }
            const float si = fmaf(0.5f, tanhapx(fmaf(0.5f, gi, hb1[j][0])), 0.5f);
            const float sf = fmaf(0.5f, tanhapx(fmaf(0.5f, gf, hb1[j][1])), 0.5f);
            const float tg = tanhapx(gg + bg1[j]);
            const float cn = fmaf(sf, cst1[j], si*tg);
            cst1[j] = cn;
            const float so = fmaf(0.5f, tanhapx(fmaf(0.5f, go, hb1[j][2])), 0.5f);
            const float hn = so * tanhapx(cn);
            if (u < Hh) {
                const uint32_t hi = to_tf32(hn);
                hbu[hidx(0, 0, bmy, u)] = hi;
                hbu[hidx(0, 1, bmy, u)] = to_tf32(hn - __uint_as_float(hi));
            }
        }
        if (tid < NB) {
            const uint32_t hi = to_tf32(xf);
            hbu[hidx(0, 0, tid, 51)] = hi;
            hbu[hidx(0, 1, tid, 51)] = to_tf32(xf - __uint_as_float(hi));
        }
        __syncthreads();
    }

    // ================= main loop: step n does L1[n+1] + L2[n] =================
    for (int n = 0; n < Lt; ++n) {
        const int rr = n & 1, wr = 1 - rr;       // R (h1+x) regions
        const int qr = 2 + rr, qw = 3 - rr;      // Q (h2) regions

        float xf = 0.f;
        const bool havex = (tid < NB) && (n + 2 < Lt);
        if (havex) xf = x[(b0 + tid)*Lt + n + 2];

        float a1[NTW][4], a2[NTW][4];
        #pragma unroll
        for (int j = 0; j < NTW; j++) {
            a1[j][0]=a1[j][1]=a1[j][2]=a1[j][3]=0.f;
            a2[j][0]=a2[j][1]=a2[j][2]=a2[j][3]=0.f;
        }
        // ---- rr chunks (h1[n] + x[n+1]) feed BOTH layers ----
        #pragma unroll
        for (int p = 0; p < 3; p++) {
            const float* ab = &hbuf[rr*RSTRIDE + (2*p)*128 + lane*4];
            const uint4 ah0 = *(const uint4*)(ab);
            const uint4 ah1 = *(const uint4*)(ab + 128);
            const uint4 al0 = *(const uint4*)(ab + NC1*128);
            const uint4 al1 = *(const uint4*)(ab + NC1*128 + 128);
            #pragma unroll
            for (int j = 0; j < NTW; j++) {
                const int tau = wid + 8*j;
                const uint4 b1v = *(const uint4*)&b1pk[tau*448 + p*128 + lane*4];
                mma8(a1[j], ah0, b1v.x, b1v.y);
                mma8(a1[j], al0, b1v.x, b1v.y);
                mma8(a1[j], ah1, b1v.z, b1v.w);
                mma8(a1[j], al1, b1v.z, b1v.w);
                const uint4 b2v = *(const uint4*)&b2pk[tau*896 + p*128 + lane*4];
                mma8(a2[j], ah0, b2v.x, b2v.y);
                mma8(a2[j], al0, b2v.x, b2v.y);
                mma8(a2[j], ah1, b2v.z, b2v.w);
                mma8(a2[j], al1, b2v.z, b2v.w);
            }
        }
        {   // rr single chunk 6
            const uint4 ah = *(const uint4*)&hbuf[rr*RSTRIDE + 6*128 + lane*4];
            const uint4 al = *(const uint4*)&hbuf[rr*RSTRIDE + NC1*128 + 6*128 + lane*4];
            #pragma unroll
            for (int j = 0; j < NTW; j++) {
                const int tau = wid + 8*j;
                const uint2 b1s = *(const uint2*)&b1pk[tau*448 + 384 + lane*2];
                mma8(a1[j], ah, b1s.x, b1s.y);
                mma8(a1[j], al, b1s.x, b1s.y);
                const uint2 b2s = *(const uint2*)&b2pk[tau*896 + 384 + lane*2];
                mma8(a2[j], ah, b2s.x, b2s.y);
                mma8(a2[j], al, b2s.x, b2s.y);
            }
        }

        // ---- L1 epilogue (overlaps with qr MMAs below in the scheduler) ----
        #pragma unroll
        for (int j = 0; j < NTW; j++) {
            const int u = 2*(wid + 8*j) + uh;
            const float sA = (tq & 1) ? a1[j][0] : a1[j][2];
            const float sB = (tq & 1) ? a1[j][1] : a1[j][3];
            const float rA = __shfl_xor_sync(0xffffffffu, sA, 1);
            const float rB = __shfl_xor_sync(0xffffffffu, sB, 1);
            float gi, gf, gg, go;
            if (tq & 1) { gi = rA; gf = rB; gg = a1[j][2]; go = a1[j][3]; }
            else        { gi = a1[j][0]; gf = a1[j][1]; gg = rA; go = rB; }
            const float si = fmaf(0.5f, tanhapx(fmaf(0.5f, gi, hb1[j][0])), 0.5f);
            const float sf = fmaf(0.5f, tanhapx(fmaf(0.5f, gf, hb1[j][1])), 0.5f);
            const float tg = tanhapx(gg + bg1[j]);
            const float cn = fmaf(sf, cst1[j], si*tg);
            cst1[j] = cn;
            const float so = fmaf(0.5f, tanhapx(fmaf(0.5f, go, hb1[j][2])), 0.5f);
            const float hn = so * tanhapx(cn);
            if (u < Hh) {
                const uint32_t hi = to_tf32(hn);
                hbu[hidx(wr, 0, bmy, u)] = hi;
                hbu[hidx(wr, 1, bmy, u)] = to_tf32(hn - __uint_as_float(hi));
            }
        }
        if (havex) {
            const uint32_t hi = to_tf32(xf);
            hbu[hidx(wr, 0, tid, 51)] = hi;
            hbu[hidx(wr, 1, tid, 51)] = to_tf32(xf - __uint_as_float(hi));
        }

        // ---- qr chunks (h2[n-1]) feed layer-2 only ----
        #pragma unroll
        for (int p = 0; p < 3; p++) {
            const float* ab = &hbuf[qr*RSTRIDE + (2*p)*128 + lane*4];
            const uint4 ah0 = *(const uint4*)(ab);
            const uint4 ah1 = *(const uint4*)(ab + 128);
            const uint4 al0 = *(const uint4*)(ab + NC1*128);
            const uint4 al1 = *(const uint4*)(ab + NC1*128 + 128);
            #pragma unroll
            for (int j = 0; j < NTW; j++) {
                const int tau = wid + 8*j;
                const uint4 b2v = *(const uint4*)&b2pk[tau*896 + 448 + p*128 + lane*4];
                mma8(a2[j], ah0, b2v.x, b2v.y);
                mma8(a2[j], al0, b2v.x, b2v.y);
                mma8(a2[j], ah1, b2v.z, b2v.w);
                mma8(a2[j], al1, b2v.z, b2v.w);
            }
        }
        {   // qr single chunk (global c=13)
            const uint4 ah = *(const uint4*)&hbuf[qr*RSTRIDE + 6*128 + lane*4];
            const uint4 al = *(const uint4*)&hbuf[qr*RSTRIDE + NC1*128 + 6*128 + lane*4];
            #pragma unroll
            for (int j = 0; j < NTW; j++) {
                const int tau = wid + 8*j;
                const uint2 b2s = *(const uint2*)&b2pk[tau*896 + 448 + 384 + lane*2];
                mma8(a2[j], ah, b2s.x, b2s.y);
                mma8(a2[j], al, b2s.x, b2s.y);
            }
        }

        // ---- L2 epilogue -> h2[n] into qw, output partial ----
        float ypart = 0.f;
        #pragma unroll
        for (int j = 0; j < NTW; j++) {
            const int u = 2*(wid + 8*j) + uh;
            const float sA = (tq & 1) ? a2[j][0] : a2[j][2];
            const float sB = (tq & 1) ? a2[j][1] : a2[j][3];
            const float rA = __shfl_xor_sync(0xffffffffu, sA, 1);
            const float rB = __shfl_xor_sync(0xffffffffu, sB, 1);
            float gi, gf, gg, go;
            if (tq & 1) { gi = rA; gf = rB; gg = a2[j][2]; go = a2[j][3]; }
            else        { gi = a2[j][0]; gf = a2[j][1]; gg = rA; go = rB; }
            const float si = fmaf(0.5f, tanhapx(fmaf(0.5f, gi, hb2[j][0])), 0.5f);
            const float sf = fmaf(0.5f, tanhapx(fmaf(0.5f, gf, hb2[j][1])), 0.5f);
            const float tg = tanhapx(gg + bg2[j]);
            const float cn = fmaf(sf, cst2[j], si*tg);
            cst2[j] = cn;
            const float so = fmaf(0.5f, tanhapx(fmaf(0.5f, go, hb2[j][2])), 0.5f);
            const float hn = so * tanhapx(cn);
            if (u < Hh) {
                const uint32_t hi = to_tf32(hn);
                hbu[hidx(qw, 0, bmy, u)] = hi;
                hbu[hidx(qw, 1, bmy, u)] = to_tf32(hn - __uint_as_float(hi));
            }
            ypart = fmaf(hn, wl[j], ypart);
        }
        const float ys = ypart + __shfl_xor_sync(0xffffffffu, ypart, 2);
        if (tq < 2) opart[(n & 1)*(WARPS*NB) + wid*NB + ((tq & 1) << 3) + gid] = ys;
        __syncthreads();   // one barrier per step

        if (tid < NB) {
            float s = sm[OFF_BLIN];
            #pragma unroll
            for (int w8 = 0; w8 < WARPS; w8++)
                s += opart[(n & 1)*(WARPS*NB) + w8*NB + tid];
            och[tid*XCHP + (n & 63)] = s;
        }

        // ---- flush output chunk (coalesced) ----
        if ((n & 63) == 63 || n == Lt-1) {
            __syncthreads();
            const int t0c = n & ~63;
            const int wd = (n & 63) + 1;
            for (int i = tid; i < NB*wd; i += THREADS) {
                const int row = i / wd, col = i - row*wd;
                out[(b0+row)*Lt + t0c + col] = och[row*XCHP + col];
            }
        }
    }
}

extern "C" void kernel_launch(void* const* d_in, const int* in_sizes, int n_in,
                              void* d_out, int out_size)
{
    const float* x     = (const float*)d_in[0];
    const float* wih1  = (const float*)d_in[1];
    const float* whh1  = (const float*)d_in[2];
    const float* bih1  = (const float*)d_in[3];
    const float* bhh1  = (const float*)d_in[4];
    const float* wih2  = (const float*)d_in[5];
    const float* whh2  = (const float*)d_in[6];
    const float* bih2  = (const float*)d_in[7];
    const float* bhh2  = (const float*)d_in[8];
    const float* wlin  = (const float*)d_in[9];
    const float* blin  = (const float*)d_in[10];
    float* out = (float*)d_out;

    const size_t smem = (size_t)SMEM_FLOATS * sizeof(float);
    cudaFuncSetAttribute(lstm_kernel, cudaFuncAttributeMaxDynamicSharedMemorySize, (int)smem);
    lstm_kernel<<<NCTA, THREADS, smem>>>(x, wih1, whh1, bih1, bhh1,
                                         wih2, whh2, bih2, bhh2,
                                         wlin, blin, out);
}

// round 13
// speedup vs baseline: 1.2640x; 1.1199x over previous
#include <cuda_runtime.h>
#include <cuda_bf16.h>
#include <cstdint>

#define Hh 51
#define Lt 999
#define NB 16
#define NCTA 128
#define THREADS 256
#define WARPS 8
#define NTW 4          // n8-tiles per warp (32 tiles total)
#define NCH1 4         // k16 chunks layer1 (K=64: h1[51] + x + pad)
#define NCH2 8         // k16 chunks layer2 (two sides of 4)
#define XCHP 65
#define PLSTRIDE 512   // words per plane (4 chunks x 128)
#define RSTRIDE 1024   // words per region (hi+lo planes)

// shared memory float offsets
#define OFF_B1PK 0
#define SZ_B1PK (32*NCH1*32*4)           // 16384
#define OFF_B2PK (OFF_B1PK + SZ_B1PK)
#define SZ_B2PK (32*NCH2*32*4)           // 32768
#define OFF_HBUF (OFF_B2PK + SZ_B2PK)    // 4 regions: R0,R1 (h1+x), Q0,Q1 (h2)
#define SZ_HBUF (4*RSTRIDE)              // 4096
#define OFF_OCH  (OFF_HBUF + SZ_HBUF)
#define OFF_OP   (OFF_OCH + NB*XCHP)     // 2 x 128 double-buffered partials
#define OFF_BLIN (OFF_OP + 2*WARPS*NB)
#define SMEM_FLOATS (OFF_BLIN + 4)

__device__ __forceinline__ void mma16(float* d, uint4 a, uint32_t b0, uint32_t b1) {
    asm("mma.sync.aligned.m16n8k16.row.col.f32.bf16.bf16.f32 "
        "{%0,%1,%2,%3}, {%4,%5,%6,%7}, {%8,%9}, {%0,%1,%2,%3};"
        : "+f"(d[0]), "+f"(d[1]), "+f"(d[2]), "+f"(d[3])
        : "r"(a.x), "r"(a.y), "r"(a.z), "r"(a.w), "r"(b0), "r"(b1));
}
__device__ __forceinline__ float tanhapx(float x) {
    float r; asm("tanh.approx.f32 %0, %1;" : "=f"(r) : "f"(x)); return r;
}
// word index for (region, plane, batch b, unit u); u16 slot = word*2 + (u&1)
__device__ __forceinline__ int widx(int region, int plane, int b, int u) {
    const int ch = u >> 4, kin = u & 15;
    const int ln = ((b & 7) << 2) + ((kin & 7) >> 1);
    const int reg = ((kin >= 8) ? 2 : 0) + ((b >= 8) ? 1 : 0);
    return region*RSTRIDE + plane*PLSTRIDE + ch*128 + ln*4 + reg;
}
__device__ __forceinline__ void store_h(uint16_t* hb16, int region, int b, int u, float v) {
    const __nv_bfloat16 hi = __float2bfloat16(v);
    const __nv_bfloat16 lo = __float2bfloat16(v - __bfloat162float(hi));
    const int h = u & 1;
    hb16[widx(region, 0, b, u)*2 + h] = __bfloat16_as_ushort(hi);
    hb16[widx(region, 1, b, u)*2 + h] = __bfloat16_as_ushort(lo);
}
__device__ __forceinline__ uint32_t pack_w(float w0, float w1, int plane) {
    const __nv_bfloat16 h0 = __float2bfloat16(w0);
    const __nv_bfloat16 h1 = __float2bfloat16(w1);
    uint16_t b0, b1;
    if (plane == 0) { b0 = __bfloat16_as_ushort(h0); b1 = __bfloat16_as_ushort(h1); }
    else {
        b0 = __bfloat16_as_ushort(__float2bfloat16(w0 - __bfloat162float(h0)));
        b1 = __bfloat16_as_ushort(__float2bfloat16(w1 - __bfloat162float(h1)));
    }
    return ((uint32_t)b1 << 16) | b0;
}

__global__ void __launch_bounds__(THREADS, 1)
lstm_kernel(const float* __restrict__ x,
            const float* __restrict__ gWih1, const float* __restrict__ gWhh1,
            const float* __restrict__ gbih1, const float* __restrict__ gbhh1,
            const float* __restrict__ gWih2, const float* __restrict__ gWhh2,
            const float* __restrict__ gbih2, const float* __restrict__ gbhh2,
            const float* __restrict__ gWlin, const float* __restrict__ gblin,
            float* __restrict__ out)
{
    extern __shared__ float sm[];
    float* b1pk = sm + OFF_B1PK;
    float* b2pk = sm + OFF_B2PK;
    float* hbuf = sm + OFF_HBUF;
    uint16_t* hb16 = (uint16_t*)hbuf;
    float* och  = sm + OFF_OCH;
    float* opart= sm + OFF_OP;

    const int tid  = threadIdx.x;
    const int wid  = tid >> 5;
    const int lane = tid & 31;
    const int gid  = lane >> 2, tq = lane & 3;
    const int bmy  = gid + ((tq & 1) << 3);   // this lane's batch
    const int uh   = tq >> 1;                 // unit half within tile
    const int b0   = blockIdx.x * NB;

    // ---- pack layer-1 weights (bf16 hi/lo fragment layout) ----
    // word: reg=idx&3 (0:hi-b0 1:hi-b1 2:lo-b0 3:lo-b1), lane, ch, tau
    for (int idx = tid; idx < SZ_B1PK; idx += THREADS) {
        const int reg = idx & 3;
        const int ln  = (idx >> 2) & 31;
        const int ch  = (idx >> 7) & (NCH1-1);
        const int tau = idx >> 9;
        const int grp = ln >> 2, tql = ln & 3;
        const int n = tau*8 + grp;
        const int u = n >> 2, ty = n & 3;
        const int kb = ch*16 + 2*tql + (reg & 1)*8;
        float w[2];
        #pragma unroll
        for (int h = 0; h < 2; h++) {
            const int k = kb + h;
            float v = 0.f;
            if (u < Hh) {
                const int R = ty*Hh + u;
                if (k < Hh)       v = gWhh1[R*Hh + k];
                else if (k == Hh) v = gWih1[R];          // x slot (unit 51)
            }
            w[h] = v;
        }
        ((uint32_t*)b1pk)[idx] = pack_w(w[0], w[1], reg >> 1);
    }
    // ---- pack layer-2 weights: chunks 0-3 = Wih2 (h1 side, x col zero), 4-7 = Whh2 ----
    for (int idx = tid; idx < SZ_B2PK; idx += THREADS) {
        const int reg = idx & 3;
        const int ln  = (idx >> 2) & 31;
        const int ch  = (idx >> 7) & (NCH2-1);
        const int tau = idx >> 10;
        const int grp = ln >> 2, tql = ln & 3;
        const int n = tau*8 + grp;
        const int u = n >> 2, ty = n & 3;
        const int kb = (ch & 3)*16 + 2*tql + (reg & 1)*8;
        float w[2];
        #pragma unroll
        for (int h = 0; h < 2; h++) {
            const int k = kb + h;
            float v = 0.f;
            if (u < Hh && k < Hh) {
                const int R = ty*Hh + u;
                v = (ch < 4) ? gWih2[R*Hh + k] : gWhh2[R*Hh + k];
            }
            w[h] = v;
        }
        ((uint32_t*)b2pk)[idx] = pack_w(w[0], w[1], reg >> 1);
    }
    for (int i = tid; i < SZ_HBUF; i += THREADS) hbuf[i] = 0.f;
    if (tid == 0) sm[OFF_BLIN] = gblin[0];
    __syncthreads();
    // x[0] into region 1 (prologue read region)
    if (tid < NB) store_h(hb16, 1, tid, 51, x[(b0 + tid)*Lt + 0]);
    // per-lane exact biases: half-bias for i,f,o (sigmoid-via-tanh), full for g
    float wl[NTW], hb1[NTW][3], bg1[NTW], hb2[NTW][3], bg2[NTW];
    #pragma unroll
    for (int j = 0; j < NTW; j++) {
        const int u = 2*(wid + 8*j) + uh;
        const bool ok = (u < Hh);
        wl[j] = ok ? gWlin[u] : 0.f;
        hb1[j][0] = ok ? 0.5f*(gbih1[u] + gbhh1[u]) : 0.f;
        hb1[j][1] = ok ? 0.5f*(gbih1[Hh+u] + gbhh1[Hh+u]) : 0.f;
        bg1[j]    = ok ? (gbih1[2*Hh+u] + gbhh1[2*Hh+u]) : 0.f;
        hb1[j][2] = ok ? 0.5f*(gbih1[3*Hh+u] + gbhh1[3*Hh+u]) : 0.f;
        hb2[j][0] = ok ? 0.5f*(gbih2[u] + gbhh2[u]) : 0.f;
        hb2[j][1] = ok ? 0.5f*(gbih2[Hh+u] + gbhh2[Hh+u]) : 0.f;
        bg2[j]    = ok ? (gbih2[2*Hh+u] + gbhh2[2*Hh+u]) : 0.f;
        hb2[j][2] = ok ? 0.5f*(gbih2[3*Hh+u] + gbhh2[3*Hh+u]) : 0.f;
    }
    float cst1[NTW] = {0.f,0.f,0.f,0.f}, cst2[NTW] = {0.f,0.f,0.f,0.f};
    __syncthreads();

    // ================= prologue: h1[0] = cell1(x[0], 0) =================
    {
        float xf = 0.f;
        if (tid < NB) xf = x[(b0 + tid)*Lt + 1];
        float a1[NTW][4];
        #pragma unroll
        for (int j = 0; j < NTW; j++) { a1[j][0]=a1[j][1]=a1[j][2]=a1[j][3]=0.f; }
        #pragma unroll
        for (int c = 0; c < NCH1; c++) {
            const uint4 ah = *(const uint4*)&hbuf[1*RSTRIDE + c*128 + lane*4];
            const uint4 al = *(const uint4*)&hbuf[1*RSTRIDE + PLSTRIDE + c*128 + lane*4];
            #pragma unroll
            for (int j = 0; j < NTW; j++) {
                const int tau = wid + 8*j;
                const uint4 bv = *(const uint4*)&b1pk[((tau*NCH1 + c)*32 + lane)*4];
                mma16(a1[j], ah, bv.x, bv.y);
                mma16(a1[j], al, bv.x, bv.y);
                mma16(a1[j], ah, bv.z, bv.w);
            }
        }
        #pragma unroll
        for (int j = 0; j < NTW; j++) {
            const int u = 2*(wid + 8*j) + uh;
            const float sA = (tq & 1) ? a1[j][0] : a1[j][2];
            const float sB = (tq & 1) ? a1[j][1] : a1[j][3];
            const float rA = __shfl_xor_sync(0xffffffffu, sA, 1);
            const float rB = __shfl_xor_sync(0xffffffffu, sB, 1);
            float gi, gf, gg, go;
            if (tq & 1) { gi = rA; gf = rB; gg = a1[j][2]; go = a1[j][3]; }
            else        { gi = a1[j][0]; gf = a1[j][1]; gg = rA; go = rB; }
            const float si = fmaf(0.5f, tanhapx(fmaf(0.5f, gi, hb1[j][0])), 0.5f);
            const float sf = fmaf(0.5f, tanhapx(fmaf(0.5f, gf, hb1[j][1])), 0.5f);
            const float tg = tanhapx(gg + bg1[j]);
            const float cn = fmaf(sf, cst1[j], si*tg);
            cst1[j] = cn;
            const float so = fmaf(0.5f, tanhapx(fmaf(0.5f, go, hb1[j][2])), 0.5f);
            const float hn = so * tanhapx(cn);
            if (u < Hh) store_h(hb16, 0, bmy, u, hn);
        }
        if (tid < NB) store_h(hb16, 0, tid, 51, xf);
        __syncthreads();
    }

    // ================= main loop: step n does L1[n+1] + L2[n] =================
    for (int n = 0; n < Lt; ++n) {
        const int rr = n & 1, wr = 1 - rr;       // R (h1+x) regions
        const int qr = 2 + rr, qw = 3 - rr;      // Q (h2) regions

        float xf = 0.f;
        const bool havex = (tid < NB) && (n + 2 < Lt);
        if (havex) xf = x[(b0 + tid)*Lt + n + 2];

        float a1[NTW][4], a2[NTW][4];
        #pragma unroll
        for (int j = 0; j < NTW; j++) {
            a1[j][0]=a1[j][1]=a1[j][2]=a1[j][3]=0.f;
            a2[j][0]=a2[j][1]=a2[j][2]=a2[j][3]=0.f;
        }
        // ---- rr chunks (h1[n] + x[n+1]) feed BOTH layers ----
        #pragma unroll
        for (int c = 0; c < NCH1; c++) {
            const uint4 ah = *(const uint4*)&hbuf[rr*RSTRIDE + c*128 + lane*4];
            const uint4 al = *(const uint4*)&hbuf[rr*RSTRIDE + PLSTRIDE + c*128 + lane*4];
            #pragma unroll
            for (int j = 0; j < NTW; j++) {
                const int tau = wid + 8*j;
                const uint4 b1v = *(const uint4*)&b1pk[((tau*NCH1 + c)*32 + lane)*4];
                mma16(a1[j], ah, b1v.x, b1v.y);
                mma16(a1[j], al, b1v.x, b1v.y);
                mma16(a1[j], ah, b1v.z, b1v.w);
                const uint4 b2v = *(const uint4*)&b2pk[((tau*NCH2 + c)*32 + lane)*4];
                mma16(a2[j], ah, b2v.x, b2v.y);
                mma16(a2[j], al, b2v.x, b2v.y);
                mma16(a2[j], ah, b2v.z, b2v.w);
            }
        }

        // ---- L1 epilogue (scheduler overlaps with qr MMAs below) ----
        #pragma unroll
        for (int j = 0; j < NTW; j++) {
            const int u = 2*(wid + 8*j) + uh;
            const float sA = (tq & 1) ? a1[j][0] : a1[j][2];
            const float sB = (tq & 1) ? a1[j][1] : a1[j][3];
            const float rA = __shfl_xor_sync(0xffffffffu, sA, 1);
            const float rB = __shfl_xor_sync(0xffffffffu, sB, 1);
            float gi, gf, gg, go;
            if (tq & 1) { gi = rA; gf = rB; gg = a1[j][2]; go = a1[j][3]; }
            else        { gi = a1[j][0]; gf = a1[j][1]; gg = rA; go = rB; }
            const float si = fmaf(0.5f, tanhapx(fmaf(0.5f, gi, hb1[j][0])), 0.5f);
            const float sf = fmaf(0.5f, tanhapx(fmaf(0.5f, gf, hb1[j][1])), 0.5f);
            const float tg = tanhapx(gg + bg1[j]);
            const float cn = fmaf(sf, cst1[j], si*tg);
            cst1[j] = cn;
            const float so = fmaf(0.5f, tanhapx(fmaf(0.5f, go, hb1[j][2])), 0.5f);
            const float hn = so * tanhapx(cn);
            if (u < Hh) store_h(hb16, wr, bmy, u, hn);
        }
        if (havex) store_h(hb16, wr, tid, 51, xf);

        // ---- qr chunks (h2[n-1]) feed layer-2 only ----
        #pragma unroll
        for (int c = 0; c < NCH1; c++) {
            const uint4 ah = *(const uint4*)&hbuf[qr*RSTRIDE + c*128 + lane*4];
            const uint4 al = *(const uint4*)&hbuf[qr*RSTRIDE + PLSTRIDE + c*128 + lane*4];
            #pragma unroll
            for (int j = 0; j < NTW; j++) {
                const int tau = wid + 8*j;
                const uint4 b2v = *(const uint4*)&b2pk[((tau*NCH2 + 4 + c)*32 + lane)*4];
                mma16(a2[j], ah, b2v.x, b2v.y);
                mma16(a2[j], al, b2v.x, b2v.y);
                mma16(a2[j], ah, b2v.z, b2v.w);
            }
        }

        // ---- L2 epilogue -> h2[n] into qw, output partial ----
        float ypart = 0.f;
        #pragma unroll
        for (int j = 0; j < NTW; j++) {
            const int u = 2*(wid + 8*j) + uh;
            const float sA = (tq & 1) ? a2[j][0] : a2[j][2];
            const float sB = (tq & 1) ? a2[j][1] : a2[j][3];
            const float rA = __shfl_xor_sync(0xffffffffu, sA, 1);
            const float rB = __shfl_xor_sync(0xffffffffu, sB, 1);
            float gi, gf, gg, go;
            if (tq & 1) { gi = rA; gf = rB; gg = a2[j][2]; go = a2[j][3]; }
            else        { gi = a2[j][0]; gf = a2[j][1]; gg = rA; go = rB; }
            const float si = fmaf(0.5f, tanhapx(fmaf(0.5f, gi, hb2[j][0])), 0.5f);
            const float sf = fmaf(0.5f, tanhapx(fmaf(0.5f, gf, hb2[j][1])), 0.5f);
            const float tg = tanhapx(gg + bg2[j]);
            const float cn = fmaf(sf, cst2[j], si*tg);
            cst2[j] = cn;
            const float so = fmaf(0.5f, tanhapx(fmaf(0.5f, go, hb2[j][2])), 0.5f);
            const float hn = so * tanhapx(cn);
            if (u < Hh) store_h(hb16, qw, bmy, u, hn);
            ypart = fmaf(hn, wl[j], ypart);
        }
        const float ys = ypart + __shfl_xor_sync(0xffffffffu, ypart, 2);
        if (tq < 2) opart[(n & 1)*(WARPS*NB) + wid*NB + ((tq & 1) << 3) + gid] = ys;
        __syncthreads();   // one barrier per step

        if (tid < NB) {
            float s = sm[OFF_BLIN];
            #pragma unroll
            for (int w8 = 0; w8 < WARPS; w8++)
                s += opart[(n & 1)*(WARPS*NB) + w8*NB + tid];
            och[tid*XCHP + (n & 63)] = s;
        }

        // ---- flush output chunk (coalesced) ----
        if ((n & 63) == 63 || n == Lt-1) {
            __syncthreads();
            const int t0c = n & ~63;
            const int wd = (n & 63) + 1;
            for (int i = tid; i < NB*wd; i += THREADS) {
                const int row = i / wd, col = i - row*wd;
                out[(b0+row)*Lt + t0c + col] = och[row*XCHP + col];
            }
        }
    }
}

extern "C" void kernel_launch(void* const* d_in, const int* in_sizes, int n_in,
                              void* d_out, int out_size)
{
    const float* x     = (const float*)d_in[0];
    const float* wih1  = (const float*)d_in[1];
    const float* whh1  = (const float*)d_in[2];
    const float* bih1  = (const float*)d_in[3];
    const float* bhh1  = (const float*)d_in[4];
    const float* wih2  = (const float*)d_in[5];
    const float* whh2  = (const float*)d_in[6];
    const float* bih2  = (const float*)d_in[7];
    const float* bhh2  = (const float*)d_in[8];
    const float* wlin  = (const float*)d_in[9];
    const float* blin  = (const float*)d_in[10];
    float* out = (float*)d_out;

    const size_t smem = (size_t)SMEM_FLOATS * sizeof(float);
    cudaFuncSetAttribute(lstm_kernel, cudaFuncAttributeMaxDynamicSharedMemorySize, (int)smem);
    lstm_kernel<<<NCTA, THREADS, smem>>>(x, wih1, whh1, bih1, bhh1,
                                         wih2, whh2, bih2, bhh2,
                                         wlin, blin, out);
}

// round 14
// speedup vs baseline: 1.7237x; 1.3636x over previous
#include <cuda_runtime.h>
#include <cuda_fp16.h>
#include <cstdint>

#define Hh 51
#define Lt 999
#define NB 16
#define NCTA 128
#define THREADS 256
#define WARPS 8
#define NTW 4          // n8-tiles per warp (32 tiles total)
#define NCH1 4         // k16 chunks layer1 (K=64: h1[51] + x + pad)
#define NCH2 8         // k16 chunks layer2 (two sides of 4)
#define XCHP 65
#define RSTRIDE 512    // words per region (single fp16-pair plane, 4 chunks x 128)

// shared memory float offsets
#define OFF_B1PK 0
#define SZ_B1PK (32*NCH1*32*4)           // 16384
#define OFF_B2PK (OFF_B1PK + SZ_B1PK)
#define SZ_B2PK (32*NCH2*32*4)           // 32768
#define OFF_HBUF (OFF_B2PK + SZ_B2PK)    // 4 regions: R0,R1 (h1+x), Q0,Q1 (h2)
#define SZ_HBUF (4*RSTRIDE)              // 2048
#define OFF_OCH  (OFF_HBUF + SZ_HBUF)
#define OFF_OP   (OFF_OCH + NB*XCHP)     // 2 x 128 double-buffered partials
#define OFF_BLIN (OFF_OP + 2*WARPS*NB)
#define SMEM_FLOATS (OFF_BLIN + 4)

__device__ __forceinline__ void mma16(float* d, uint4 a, uint32_t b0, uint32_t b1) {
    asm("mma.sync.aligned.m16n8k16.row.col.f32.f16.f16.f32 "
        "{%0,%1,%2,%3}, {%4,%5,%6,%7}, {%8,%9}, {%0,%1,%2,%3};"
        : "+f"(d[0]), "+f"(d[1]), "+f"(d[2]), "+f"(d[3])
        : "r"(a.x), "r"(a.y), "r"(a.z), "r"(a.w), "r"(b0), "r"(b1));
}
__device__ __forceinline__ float tanhapx(float x) {
    float r; asm("tanh.approx.f32 %0, %1;" : "=f"(r) : "f"(x)); return r;
}
// word index for (region, batch b, unit u); u16 slot = word*2 + (u&1)
__device__ __forceinline__ int widx(int region, int b, int u) {
    const int ch = u >> 4, kin = u & 15;
    const int ln = ((b & 7) << 2) + ((kin & 7) >> 1);
    const int reg = ((kin >= 8) ? 2 : 0) + ((b >= 8) ? 1 : 0);
    return region*RSTRIDE + ch*128 + ln*4 + reg;
}
__device__ __forceinline__ void store_h(uint16_t* hb16, int region, int b, int u, float v) {
    hb16[widx(region, b, u)*2 + (u & 1)] = __half_as_ushort(__float2half_rn(v));
}
// pack two adjacent-k weights into one u32; plane 0 = hi, 1 = residual lo
__device__ __forceinline__ uint32_t pack_w(float w0, float w1, int plane) {
    const __half h0 = __float2half_rn(w0);
    const __half h1 = __float2half_rn(w1);
    uint16_t b0, b1;
    if (plane == 0) { b0 = __half_as_ushort(h0); b1 = __half_as_ushort(h1); }
    else {
        b0 = __half_as_ushort(__float2half_rn(w0 - __half2float(h0)));
        b1 = __half_as_ushort(__float2half_rn(w1 - __half2float(h1)));
    }
    return ((uint32_t)b1 << 16) | b0;
}

__global__ void __launch_bounds__(THREADS, 1)
lstm_kernel(const float* __restrict__ x,
            const float* __restrict__ gWih1, const float* __restrict__ gWhh1,
            const float* __restrict__ gbih1, const float* __restrict__ gbhh1,
            const float* __restrict__ gWih2, const float* __restrict__ gWhh2,
            const float* __restrict__ gbih2, const float* __restrict__ gbhh2,
            const float* __restrict__ gWlin, const float* __restrict__ gblin,
            float* __restrict__ out)
{
    extern __shared__ float sm[];
    float* b1pk = sm + OFF_B1PK;
    float* b2pk = sm + OFF_B2PK;
    float* hbuf = sm + OFF_HBUF;
    uint16_t* hb16 = (uint16_t*)hbuf;
    float* och  = sm + OFF_OCH;
    float* opart= sm + OFF_OP;

    const int tid  = threadIdx.x;
    const int wid  = tid >> 5;
    const int lane = tid & 31;
    const int gid  = lane >> 2, tq = lane & 3;
    const int bmy  = gid + ((tq & 1) << 3);   // this lane's batch
    const int uh   = tq >> 1;                 // unit half within tile
    const int b0   = blockIdx.x * NB;

    // ---- pack layer-1 weights (fp16 hi/lo fragment layout) ----
    // word: reg=idx&3 (0:hi-b0 1:hi-b1 2:lo-b0 3:lo-b1), lane, ch, tau
    for (int idx = tid; idx < SZ_B1PK; idx += THREADS) {
        const int reg = idx & 3;
        const int ln  = (idx >> 2) & 31;
        const int ch  = (idx >> 7) & (NCH1-1);
        const int tau = idx >> 9;
        const int grp = ln >> 2, tql = ln & 3;
        const int n = tau*8 + grp;
        const int u = n >> 2, ty = n & 3;
        const int kb = ch*16 + 2*tql + (reg & 1)*8;
        float w[2];
        #pragma unroll
        for (int h = 0; h < 2; h++) {
            const int k = kb + h;
            float v = 0.f;
            if (u < Hh) {
                const int R = ty*Hh + u;
                if (k < Hh)       v = gWhh1[R*Hh + k];
                else if (k == Hh) v = gWih1[R];          // x slot (unit 51)
            }
            w[h] = v;
        }
        ((uint32_t*)b1pk)[idx] = pack_w(w[0], w[1], reg >> 1);
    }
    // ---- pack layer-2 weights: chunks 0-3 = Wih2 (h1 side), 4-7 = Whh2 ----
    for (int idx = tid; idx < SZ_B2PK; idx += THREADS) {
        const int reg = idx & 3;
        const int ln  = (idx >> 2) & 31;
        const int ch  = (idx >> 7) & (NCH2-1);
        const int tau = idx >> 10;
        const int grp = ln >> 2, tql = ln & 3;
        const int n = tau*8 + grp;
        const int u = n >> 2, ty = n & 3;
        const int kb = (ch & 3)*16 + 2*tql + (reg & 1)*8;
        float w[2];
        #pragma unroll
        for (int h = 0; h < 2; h++) {
            const int k = kb + h;
            float v = 0.f;
            if (u < Hh && k < Hh) {
                const int R = ty*Hh + u;
                v = (ch < 4) ? gWih2[R*Hh + k] : gWhh2[R*Hh + k];
            }
            w[h] = v;
        }
        ((uint32_t*)b2pk)[idx] = pack_w(w[0], w[1], reg >> 1);
    }
    for (int i = tid; i < SZ_HBUF; i += THREADS) hbuf[i] = 0.f;
    if (tid == 0) sm[OFF_BLIN] = gblin[0];
    __syncthreads();
    // x[0] into region 1 (prologue read region)
    if (tid < NB) store_h(hb16, 1, tid, 51, x[(b0 + tid)*Lt + 0]);
    // per-lane exact biases: half-bias for i,f,o (sigmoid-via-tanh), full for g
    float wl[NTW], hb1[NTW][3], bg1[NTW], hb2[NTW][3], bg2[NTW];
    #pragma unroll
    for (int j = 0; j < NTW; j++) {
        const int u = 2*(wid + 8*j) + uh;
        const bool ok = (u < Hh);
        wl[j] = ok ? gWlin[u] : 0.f;
        hb1[j][0] = ok ? 0.5f*(gbih1[u] + gbhh1[u]) : 0.f;
        hb1[j][1] = ok ? 0.5f*(gbih1[Hh+u] + gbhh1[Hh+u]) : 0.f;
        bg1[j]    = ok ? (gbih1[2*Hh+u] + gbhh1[2*Hh+u]) : 0.f;
        hb1[j][2] = ok ? 0.5f*(gbih1[3*Hh+u] + gbhh1[3*Hh+u]) : 0.f;
        hb2[j][0] = ok ? 0.5f*(gbih2[u] + gbhh2[u]) : 0.f;
        hb2[j][1] = ok ? 0.5f*(gbih2[Hh+u] + gbhh2[Hh+u]) : 0.f;
        bg2[j]    = ok ? (gbih2[2*Hh+u] + gbhh2[2*Hh+u]) : 0.f;
        hb2[j][2] = ok ? 0.5f*(gbih2[3*Hh+u] + gbhh2[3*Hh+u]) : 0.f;
    }
    float cst1[NTW] = {0.f,0.f,0.f,0.f}, cst2[NTW] = {0.f,0.f,0.f,0.f};
    __syncthreads();

    // ---- hoist qr-side B2 fragments (Whh2) into registers (loop-invariant) ----
    uint4 B2R[NTW][NCH1];
    #pragma unroll
    for (int j = 0; j < NTW; j++) {
        const int tau = wid + 8*j;
        #pragma unroll
        for (int c = 0; c < NCH1; c++)
            B2R[j][c] = *(const uint4*)&b2pk[((tau*NCH2 + 4 + c)*32 + lane)*4];
    }

    // ================= prologue: h1[0] = cell1(x[0], 0) =================
    {
        float xf = 0.f;
        if (tid < NB) xf = x[(b0 + tid)*Lt + 1];
        float a1[NTW][4];
        #pragma unroll
        for (int j = 0; j < NTW; j++) { a1[j][0]=a1[j][1]=a1[j][2]=a1[j][3]=0.f; }
        #pragma unroll
        for (int c = 0; c < NCH1; c++) {
            const uint4 ah = *(const uint4*)&hbuf[1*RSTRIDE + c*128 + lane*4];
            #pragma unroll
            for (int j = 0; j < NTW; j++) {
                const int tau = wid + 8*j;
                const uint4 bv = *(const uint4*)&b1pk[((tau*NCH1 + c)*32 + lane)*4];
                mma16(a1[j], ah, bv.x, bv.y);   // Whi . h
                mma16(a1[j], ah, bv.z, bv.w);   // Wlo . h
            }
        }
        #pragma unroll
        for (int j = 0; j < NTW; j++) {
            const int u = 2*(wid + 8*j) + uh;
            const float sA = (tq & 1) ? a1[j][0] : a1[j][2];
            const float sB = (tq & 1) ? a1[j][1] : a1[j][3];
            const float rA = __shfl_xor_sync(0xffffffffu, sA, 1);
            const float rB = __shfl_xor_sync(0xffffffffu, sB, 1);
            float gi, gf, gg, go;
            if (tq & 1) { gi = rA; gf = rB; gg = a1[j][2]; go = a1[j][3]; }
            else        { gi = a1[j][0]; gf = a1[j][1]; gg = rA; go = rB; }
            const float si = fmaf(0.5f, tanhapx(fmaf(0.5f, gi, hb1[j][0])), 0.5f);
            const float sf = fmaf(0.5f, tanhapx(fmaf(0.5f, gf, hb1[j][1])), 0.5f);
            const float tg = tanhapx(gg + bg1[j]);
            const float cn = fmaf(sf, cst1[j], si*tg);
            cst1[j] = cn;
            const float so = fmaf(0.5f, tanhapx(fmaf(0.5f, go, hb1[j][2])), 0.5f);
            const float hn = so * tanhapx(cn);
            if (u < Hh) store_h(hb16, 0, bmy, u, hn);
        }
        if (tid < NB) store_h(hb16, 0, tid, 51, xf);
        __syncthreads();
    }

    // ================= main loop: step n does L1[n+1] + L2[n] =================
    for (int n = 0; n < Lt; ++n) {
        const int rr = n & 1, wr = 1 - rr;       // R (h1+x) regions
        const int qr = 2 + rr, qw = 3 - rr;      // Q (h2) regions

        float xf = 0.f;
        const bool havex = (tid < NB) && (n + 2 < Lt);
        if (havex) xf = x[(b0 + tid)*Lt + n + 2];

        float a1[NTW][4], a2[NTW][4];
        #pragma unroll
        for (int j = 0; j < NTW; j++) {
            a1[j][0]=a1[j][1]=a1[j][2]=a1[j][3]=0.f;
            a2[j][0]=a2[j][1]=a2[j][2]=a2[j][3]=0.f;
        }
        // ---- rr chunks (h1[n] + x[n+1]) feed BOTH layers ----
        #pragma unroll
        for (int c = 0; c < NCH1; c++) {
            const uint4 ah = *(const uint4*)&hbuf[rr*RSTRIDE + c*128 + lane*4];
            #pragma unroll
            for (int j = 0; j < NTW; j++) {
                const int tau = wid + 8*j;
                const uint4 b1v = *(const uint4*)&b1pk[((tau*NCH1 + c)*32 + lane)*4];
                mma16(a1[j], ah, b1v.x, b1v.y);
                mma16(a1[j], ah, b1v.z, b1v.w);
                const uint4 b2v = *(const uint4*)&b2pk[((tau*NCH2 + c)*32 + lane)*4];
                mma16(a2[j], ah, b2v.x, b2v.y);
                mma16(a2[j], ah, b2v.z, b2v.w);
            }
        }

        // ---- L1 epilogue (scheduler overlaps with qr MMAs below) ----
        #pragma unroll
        for (int j = 0; j < NTW; j++) {
            const int u = 2*(wid + 8*j) + uh;
            const float sA = (tq & 1) ? a1[j][0] : a1[j][2];
            const float sB = (tq & 1) ? a1[j][1] : a1[j][3];
            const float rA = __shfl_xor_sync(0xffffffffu, sA, 1);
            const float rB = __shfl_xor_sync(0xffffffffu, sB, 1);
            float gi, gf, gg, go;
            if (tq & 1) { gi = rA; gf = rB; gg = a1[j][2]; go = a1[j][3]; }
            else        { gi = a1[j][0]; gf = a1[j][1]; gg = rA; go = rB; }
            const float si = fmaf(0.5f, tanhapx(fmaf(0.5f, gi, hb1[j][0])), 0.5f);
            const float sf = fmaf(0.5f, tanhapx(fmaf(0.5f, gf, hb1[j][1])), 0.5f);
            const float tg = tanhapx(gg + bg1[j]);
            const float cn = fmaf(sf, cst1[j], si*tg);
            cst1[j] = cn;
            const float so = fmaf(0.5f, tanhapx(fmaf(0.5f, go, hb1[j][2])), 0.5f);
            const float hn = so * tanhapx(cn);
            if (u < Hh) store_h(hb16, wr, bmy, u, hn);
        }
        if (havex) store_h(hb16, wr, tid, 51, xf);

        // ---- qr chunks (h2[n-1]) feed layer-2, B from registers ----
        #pragma unroll
        for (int c = 0; c < NCH1; c++) {
            const uint4 ah = *(const uint4*)&hbuf[qr*RSTRIDE + c*128 + lane*4];
            #pragma unroll
            for (int j = 0; j < NTW; j++) {
                mma16(a2[j], ah, B2R[j][c].x, B2R[j][c].y);
                mma16(a2[j], ah, B2R[j][c].z, B2R[j][c].w);
            }
        }

        // ---- L2 epilogue -> h2[n] into qw, output partial ----
        float ypart = 0.f;
        #pragma unroll
        for (int j = 0; j < NTW; j++) {
            const int u = 2*(wid + 8*j) + uh;
            const float sA = (tq & 1) ? a2[j][0] : a2[j][2];
            const float sB = (tq & 1) ? a2[j][1] : a2[j][3];
            const float rA = __shfl_xor_sync(0xffffffffu, sA, 1);
            const float rB = __shfl_xor_sync(0xffffffffu, sB, 1);
            float gi, gf, gg, go;
            if (tq & 1) { gi = rA; gf = rB; gg = a2[j][2]; go = a2[j][3]; }
            else        { gi = a2[j][0]; gf = a2[j][1]; gg = rA; go = rB; }
            const float si = fmaf(0.5f, tanhapx(fmaf(0.5f, gi, hb2[j][0])), 0.5f);
            const float sf = fmaf(0.5f, tanhapx(fmaf(0.5f, gf, hb2[j][1])), 0.5f);
            const float tg = tanhapx(gg + bg2[j]);
            const float cn = fmaf(sf, cst2[j], si*tg);
            cst2[j] = cn;
            const float so = fmaf(0.5f, tanhapx(fmaf(0.5f, go, hb2[j][2])), 0.5f);
            const float hn = so * tanhapx(cn);
            if (u < Hh) store_h(hb16, qw, bmy, u, hn);
            ypart = fmaf(hn, wl[j], ypart);
        }
        const float ys = ypart + __shfl_xor_sync(0xffffffffu, ypart, 2);
        if (tq < 2) opart[(n & 1)*(WARPS*NB) + wid*NB + ((tq & 1) << 3) + gid] = ys;
        __syncthreads();   // one barrier per step

        if (tid < NB) {
            float s = sm[OFF_BLIN];
            #pragma unroll
            for (int w8 = 0; w8 < WARPS; w8++)
                s += opart[(n & 1)*(WARPS*NB) + w8*NB + tid];
            och[tid*XCHP + (n & 63)] = s;
        }

        // ---- flush output chunk (coalesced) ----
        if ((n & 63) == 63 || n == Lt-1) {
            __syncthreads();
            const int t0c = n & ~63;
            const int wd = (n & 63) + 1;
            for (int i = tid; i < NB*wd; i += THREADS) {
                const int row = i / wd, col = i - row*wd;
                out[(b0+row)*Lt + t0c + col] = och[row*XCHP + col];
            }
        }
    }
}

extern "C" void kernel_launch(void* const* d_in, const int* in_sizes, int n_in,
                              void* d_out, int out_size)
{
    const float* x     = (const float*)d_in[0];
    const float* wih1  = (const float*)d_in[1];
    const float* whh1  = (const float*)d_in[2];
    const float* bih1  = (const float*)d_in[3];
    const float* bhh1  = (const float*)d_in[4];
    const float* wih2  = (const float*)d_in[5];
    const float* whh2  = (const float*)d_in[6];
    const float* bih2  = (const float*)d_in[7];
    const float* bhh2  = (const float*)d_in[8];
    const float* wlin  = (const float*)d_in[9];
    const float* blin  = (const float*)d_in[10];
    float* out = (float*)d_out;

    const size_t smem = (size_t)SMEM_FLOATS * sizeof(float);
    cudaFuncSetAttribute(lstm_kernel, cudaFuncAttributeMaxDynamicSharedMemorySize, (int)smem);
    lstm_kernel<<<NCTA, THREADS, smem>>>(x, wih1, whh1, bih1, bhh1,
                                         wih2, whh2, bih2, bhh2,
                                         wlin, blin, out);
}

// round 15
// speedup vs baseline: 1.8326x; 1.0632x over previous
#include <cuda_runtime.h>
#include <cuda_fp16.h>
#include <cstdint>

#define Hh 51
#define Lt 999
#define NB 16
#define NCTA 128
#define THREADS 512
#define WARPS 16
#define NTW 2          // n8-tiles per warp (32 tiles total)
#define NCH1 4         // k16 chunks layer1 (K=64: h1[51] + x + pad)
#define NCH2 8         // k16 chunks layer2 (two sides of 4)
#define XCHP 65
#define RSTRIDE 512    // words per region (single fp16-pair plane, 4 chunks x 128)

// shared memory float offsets
#define OFF_B1PK 0
#define SZ_B1PK (32*NCH1*32*4)           // 16384
#define OFF_B2PK (OFF_B1PK + SZ_B1PK)
#define SZ_B2PK (32*NCH2*32*4)           // 32768
#define OFF_HBUF (OFF_B2PK + SZ_B2PK)    // 4 regions: R0,R1 (h1+x), Q0,Q1 (h2)
#define SZ_HBUF (4*RSTRIDE)              // 2048
#define OFF_OCH  (OFF_HBUF + SZ_HBUF)
#define OFF_OP   (OFF_OCH + NB*XCHP)     // 2 x 256 double-buffered partials
#define OFF_BLIN (OFF_OP + 2*WARPS*NB)
#define SMEM_FLOATS (OFF_BLIN + 4)

__device__ __forceinline__ void mma16(float* d, uint4 a, uint32_t b0, uint32_t b1) {
    asm("mma.sync.aligned.m16n8k16.row.col.f32.f16.f16.f32 "
        "{%0,%1,%2,%3}, {%4,%5,%6,%7}, {%8,%9}, {%0,%1,%2,%3};"
        : "+f"(d[0]), "+f"(d[1]), "+f"(d[2]), "+f"(d[3])
        : "r"(a.x), "r"(a.y), "r"(a.z), "r"(a.w), "r"(b0), "r"(b1));
}
__device__ __forceinline__ float tanhapx(float x) {
    float r; asm("tanh.approx.f32 %0, %1;" : "=f"(r) : "f"(x)); return r;
}
// word index for (region, batch b, unit u); u16 slot = word*2 + (u&1)
__device__ __forceinline__ int widx(int region, int b, int u) {
    const int ch = u >> 4, kin = u & 15;
    const int ln = ((b & 7) << 2) + ((kin & 7) >> 1);
    const int reg = ((kin >= 8) ? 2 : 0) + ((b >= 8) ? 1 : 0);
    return region*RSTRIDE + ch*128 + ln*4 + reg;
}
__device__ __forceinline__ void store_h(uint16_t* hb16, int region, int b, int u, float v) {
    hb16[widx(region, b, u)*2 + (u & 1)] = __half_as_ushort(__float2half_rn(v));
}
// pack two adjacent-k weights into one u32; plane 0 = hi, 1 = residual lo
__device__ __forceinline__ uint32_t pack_w(float w0, float w1, int plane) {
    const __half h0 = __float2half_rn(w0);
    const __half h1 = __float2half_rn(w1);
    uint16_t b0, b1;
    if (plane == 0) { b0 = __half_as_ushort(h0); b1 = __half_as_ushort(h1); }
    else {
        b0 = __half_as_ushort(__float2half_rn(w0 - __half2float(h0)));
        b1 = __half_as_ushort(__float2half_rn(w1 - __half2float(h1)));
    }
    return ((uint32_t)b1 << 16) | b0;
}

__global__ void __launch_bounds__(THREADS, 1)
lstm_kernel(const float* __restrict__ x,
            const float* __restrict__ gWih1, const float* __restrict__ gWhh1,
            const float* __restrict__ gbih1, const float* __restrict__ gbhh1,
            const float* __restrict__ gWih2, const float* __restrict__ gWhh2,
            const float* __restrict__ gbih2, const float* __restrict__ gbhh2,
            const float* __restrict__ gWlin, const float* __restrict__ gblin,
            float* __restrict__ out)
{
    extern __shared__ float sm[];
    float* b1pk = sm + OFF_B1PK;
    float* b2pk = sm + OFF_B2PK;
    float* hbuf = sm + OFF_HBUF;
    uint16_t* hb16 = (uint16_t*)hbuf;
    float* och  = sm + OFF_OCH;
    float* opart= sm + OFF_OP;

    const int tid  = threadIdx.x;
    const int wid  = tid >> 5;
    const int lane = tid & 31;
    const int gid  = lane >> 2, tq = lane & 3;
    const int bmy  = gid + ((tq & 1) << 3);   // this lane's batch
    const int uh   = tq >> 1;                 // unit half within tile
    const int b0   = blockIdx.x * NB;

    // ---- pack layer-1 weights (fp16 hi/lo fragment layout) ----
    for (int idx = tid; idx < SZ_B1PK; idx += THREADS) {
        const int reg = idx & 3;
        const int ln  = (idx >> 2) & 31;
        const int ch  = (idx >> 7) & (NCH1-1);
        const int tau = idx >> 9;
        const int grp = ln >> 2, tql = ln & 3;
        const int n = tau*8 + grp;
        const int u = n >> 2, ty = n & 3;
        const int kb = ch*16 + 2*tql + (reg & 1)*8;
        float w[2];
        #pragma unroll
        for (int h = 0; h < 2; h++) {
            const int k = kb + h;
            float v = 0.f;
            if (u < Hh) {
                const int R = ty*Hh + u;
                if (k < Hh)       v = gWhh1[R*Hh + k];
                else if (k == Hh) v = gWih1[R];          // x slot (unit 51)
            }
            w[h] = v;
        }
        ((uint32_t*)b1pk)[idx] = pack_w(w[0], w[1], reg >> 1);
    }
    // ---- pack layer-2 weights: chunks 0-3 = Wih2 (h1 side), 4-7 = Whh2 ----
    for (int idx = tid; idx < SZ_B2PK; idx += THREADS) {
        const int reg = idx & 3;
        const int ln  = (idx >> 2) & 31;
        const int ch  = (idx >> 7) & (NCH2-1);
        const int tau = idx >> 10;
        const int grp = ln >> 2, tql = ln & 3;
        const int n = tau*8 + grp;
        const int u = n >> 2, ty = n & 3;
        const int kb = (ch & 3)*16 + 2*tql + (reg & 1)*8;
        float w[2];
        #pragma unroll
        for (int h = 0; h < 2; h++) {
            const int k = kb + h;
            float v = 0.f;
            if (u < Hh && k < Hh) {
                const int R = ty*Hh + u;
                v = (ch < 4) ? gWih2[R*Hh + k] : gWhh2[R*Hh + k];
            }
            w[h] = v;
        }
        ((uint32_t*)b2pk)[idx] = pack_w(w[0], w[1], reg >> 1);
    }
    for (int i = tid; i < SZ_HBUF; i += THREADS) hbuf[i] = 0.f;
    if (tid == 0) sm[OFF_BLIN] = gblin[0];
    __syncthreads();
    // x[0] into region 1 (prologue read region)
    if (tid < NB) store_h(hb16, 1, tid, 51, x[(b0 + tid)*Lt + 0]);
    // per-lane exact biases: half-bias for i,f,o (sigmoid-via-tanh), full for g
    float wl[NTW], hb1[NTW][3], bg1[NTW], hb2[NTW][3], bg2[NTW];
    #pragma unroll
    for (int j = 0; j < NTW; j++) {
        const int u = 2*(wid + 16*j) + uh;
        const bool ok = (u < Hh);
        wl[j] = ok ? gWlin[u] : 0.f;
        hb1[j][0] = ok ? 0.5f*(gbih1[u] + gbhh1[u]) : 0.f;
        hb1[j][1] = ok ? 0.5f*(gbih1[Hh+u] + gbhh1[Hh+u]) : 0.f;
        bg1[j]    = ok ? (gbih1[2*Hh+u] + gbhh1[2*Hh+u]) : 0.f;
        hb1[j][2] = ok ? 0.5f*(gbih1[3*Hh+u] + gbhh1[3*Hh+u]) : 0.f;
        hb2[j][0] = ok ? 0.5f*(gbih2[u] + gbhh2[u]) : 0.f;
        hb2[j][1] = ok ? 0.5f*(gbih2[Hh+u] + gbhh2[Hh+u]) : 0.f;
        bg2[j]    = ok ? (gbih2[2*Hh+u] + gbhh2[2*Hh+u]) : 0.f;
        hb2[j][2] = ok ? 0.5f*(gbih2[3*Hh+u] + gbhh2[3*Hh+u]) : 0.f;
    }
    float cst1[NTW] = {0.f,0.f}, cst2[NTW] = {0.f,0.f};
    __syncthreads();

    // ---- hoist qr-side B2 fragments (Whh2) into registers (loop-invariant) ----
    uint4 B2R[NTW][NCH1];
    #pragma unroll
    for (int j = 0; j < NTW; j++) {
        const int tau = wid + 16*j;
        #pragma unroll
        for (int c = 0; c < NCH1; c++)
            B2R[j][c] = *(const uint4*)&b2pk[((tau*NCH2 + 4 + c)*32 + lane)*4];
    }

    // ================= prologue: h1[0] = cell1(x[0], 0) =================
    {
        float xf = 0.f;
        if (tid < NB) xf = x[(b0 + tid)*Lt + 1];
        float a1[NTW][4];
        #pragma unroll
        for (int j = 0; j < NTW; j++) { a1[j][0]=a1[j][1]=a1[j][2]=a1[j][3]=0.f; }
        #pragma unroll
        for (int c = 0; c < NCH1; c++) {
            const uint4 ah = *(const uint4*)&hbuf[1*RSTRIDE + c*128 + lane*4];
            #pragma unroll
            for (int j = 0; j < NTW; j++) {
                const int tau = wid + 16*j;
                const uint4 bv = *(const uint4*)&b1pk[((tau*NCH1 + c)*32 + lane)*4];
                mma16(a1[j], ah, bv.x, bv.y);   // Whi . h
                mma16(a1[j], ah, bv.z, bv.w);   // Wlo . h
            }
        }
        #pragma unroll
        for (int j = 0; j < NTW; j++) {
            const int u = 2*(wid + 16*j) + uh;
            const float sA = (tq & 1) ? a1[j][0] : a1[j][2];
            const float sB = (tq & 1) ? a1[j][1] : a1[j][3];
            const float rA = __shfl_xor_sync(0xffffffffu, sA, 1);
            const float rB = __shfl_xor_sync(0xffffffffu, sB, 1);
            float gi, gf, gg, go;
            if (tq & 1) { gi = rA; gf = rB; gg = a1[j][2]; go = a1[j][3]; }
            else        { gi = a1[j][0]; gf = a1[j][1]; gg = rA; go = rB; }
            const float si = fmaf(0.5f, tanhapx(fmaf(0.5f, gi, hb1[j][0])), 0.5f);
            const float sf = fmaf(0.5f, tanhapx(fmaf(0.5f, gf, hb1[j][1])), 0.5f);
            const float tg = tanhapx(gg + bg1[j]);
            const float cn = fmaf(sf, cst1[j], si*tg);
            cst1[j] = cn;
            const float so = fmaf(0.5f, tanhapx(fmaf(0.5f, go, hb1[j][2])), 0.5f);
            const float hn = so * tanhapx(cn);
            if (u < Hh) store_h(hb16, 0, bmy, u, hn);
        }
        if (tid < NB) store_h(hb16, 0, tid, 51, xf);
        __syncthreads();
    }

    // ================= main loop: step n does L1[n+1] + L2[n] =================
    for (int n = 0; n < Lt; ++n) {
        const int rr = n & 1, wr = 1 - rr;       // R (h1+x) regions
        const int qr = 2 + rr, qw = 3 - rr;      // Q (h2) regions

        float xf = 0.f;
        const bool havex = (tid < NB) && (n + 2 < Lt);
        if (havex) xf = x[(b0 + tid)*Lt + n + 2];

        float a1[NTW][4], a2[NTW][4];
        #pragma unroll
        for (int j = 0; j < NTW; j++) {
            a1[j][0]=a1[j][1]=a1[j][2]=a1[j][3]=0.f;
            a2[j][0]=a2[j][1]=a2[j][2]=a2[j][3]=0.f;
        }
        // ---- rr chunks (h1[n] + x[n+1]) feed BOTH layers ----
        #pragma unroll
        for (int c = 0; c < NCH1; c++) {
            const uint4 ah = *(const uint4*)&hbuf[rr*RSTRIDE + c*128 + lane*4];
            #pragma unroll
            for (int j = 0; j < NTW; j++) {
                const int tau = wid + 16*j;
                const uint4 b1v = *(const uint4*)&b1pk[((tau*NCH1 + c)*32 + lane)*4];
                mma16(a1[j], ah, b1v.x, b1v.y);
                mma16(a1[j], ah, b1v.z, b1v.w);
                const uint4 b2v = *(const uint4*)&b2pk[((tau*NCH2 + c)*32 + lane)*4];
                mma16(a2[j], ah, b2v.x, b2v.y);
                mma16(a2[j], ah, b2v.z, b2v.w);
            }
        }

        // ---- L1 epilogue (scheduler overlaps with qr MMAs below) ----
        #pragma unroll
        for (int j = 0; j < NTW; j++) {
            const int u = 2*(wid + 16*j) + uh;
            const float sA = (tq & 1) ? a1[j][0] : a1[j][2];
            const float sB = (tq & 1) ? a1[j][1] : a1[j][3];
            const float rA = __shfl_xor_sync(0xffffffffu, sA, 1);
            const float rB = __shfl_xor_sync(0xffffffffu, sB, 1);
            float gi, gf, gg, go;
            if (tq & 1) { gi = rA; gf = rB; gg = a1[j][2]; go = a1[j][3]; }
            else        { gi = a1[j][0]; gf = a1[j][1]; gg = rA; go = rB; }
            const float si = fmaf(0.5f, tanhapx(fmaf(0.5f, gi, hb1[j][0])), 0.5f);
            const float sf = fmaf(0.5f, tanhapx(fmaf(0.5f, gf, hb1[j][1])), 0.5f);
            const float tg = tanhapx(gg + bg1[j]);
            const float cn = fmaf(sf, cst1[j], si*tg);
            cst1[j] = cn;
            const float so = fmaf(0.5f, tanhapx(fmaf(0.5f, go, hb1[j][2])), 0.5f);
            const float hn = so * tanhapx(cn);
            if (u < Hh) store_h(hb16, wr, bmy, u, hn);
        }
        if (havex) store_h(hb16, wr, tid, 51, xf);

        // ---- qr chunks (h2[n-1]) feed layer-2, B from registers ----
        #pragma unroll
        for (int c = 0; c < NCH1; c++) {
            const uint4 ah = *(const uint4*)&hbuf[qr*RSTRIDE + c*128 + lane*4];
            #pragma unroll
            for (int j = 0; j < NTW; j++) {
                mma16(a2[j], ah, B2R[j][c].x, B2R[j][c].y);
                mma16(a2[j], ah, B2R[j][c].z, B2R[j][c].w);
            }
        }

        // ---- L2 epilogue -> h2[n] into qw, output partial ----
        float ypart = 0.f;
        #pragma unroll
        for (int j = 0; j < NTW; j++) {
            const int u = 2*(wid + 16*j) + uh;
            const float sA = (tq & 1) ? a2[j][0] : a2[j][2];
            const float sB = (tq & 1) ? a2[j][1] : a2[j][3];
            const float rA = __shfl_xor_sync(0xffffffffu, sA, 1);
            const float rB = __shfl_xor_sync(0xffffffffu, sB, 1);
            float gi, gf, gg, go;
            if (tq & 1) { gi = rA; gf = rB; gg = a2[j][2]; go = a2[j][3]; }
            else        { gi = a2[j][0]; gf = a2[j][1]; gg = rA; go = rB; }
            const float si = fmaf(0.5f, tanhapx(fmaf(0.5f, gi, hb2[j][0])), 0.5f);
            const float sf = fmaf(0.5f, tanhapx(fmaf(0.5f, gf, hb2[j][1])), 0.5f);
            const float tg = tanhapx(gg + bg2[j]);
            const float cn = fmaf(sf, cst2[j], si*tg);
            cst2[j] = cn;
            const float so = fmaf(0.5f, tanhapx(fmaf(0.5f, go, hb2[j][2])), 0.5f);
            const float hn = so * tanhapx(cn);
            if (u < Hh) store_h(hb16, qw, bmy, u, hn);
            ypart = fmaf(hn, wl[j], ypart);
        }
        const float ys = ypart + __shfl_xor_sync(0xffffffffu, ypart, 2);
        if (tq < 2) opart[(n & 1)*(WARPS*NB) + wid*NB + ((tq & 1) << 3) + gid] = ys;
        __syncthreads();   // one barrier per step

        if (tid < NB) {
            float s = sm[OFF_BLIN];
            #pragma unroll
            for (int w8 = 0; w8 < WARPS; w8++)
                s += opart[(n & 1)*(WARPS*NB) + w8*NB + tid];
            och[tid*XCHP + (n & 63)] = s;
        }

        // ---- flush output chunk (coalesced) ----
        if ((n & 63) == 63 || n == Lt-1) {
            __syncthreads();
            const int t0c = n & ~63;
            const int wd = (n & 63) + 1;
            for (int i = tid; i < NB*wd; i += THREADS) {
                const int row = i / wd, col = i - row*wd;
                out[(b0+row)*Lt + t0c + col] = och[row*XCHP + col];
            }
        }
    }
}

extern "C" void kernel_launch(void* const* d_in, const int* in_sizes, int n_in,
                              void* d_out, int out_size)
{
    const float* x     = (const float*)d_in[0];
    const float* wih1  = (const float*)d_in[1];
    const float* whh1  = (const float*)d_in[2];
    const float* bih1  = (const float*)d_in[3];
    const float* bhh1  = (const float*)d_in[4];
    const float* wih2  = (const float*)d_in[5];
    const float* whh2  = (const float*)d_in[6];
    const float* bih2  = (const float*)d_in[7];
    const float* bhh2  = (const float*)d_in[8];
    const float* wlin  = (const float*)d_in[9];
    const float* blin  = (const float*)d_in[10];
    float* out = (float*)d_out;

    const size_t smem = (size_t)SMEM_FLOATS * sizeof(float);
    cudaFuncSetAttribute(lstm_kernel, cudaFuncAttributeMaxDynamicSharedMemorySize, (int)smem);
    lstm_kernel<<<NCTA, THREADS, smem>>>(x, wih1, whh1, bih1, bhh1,
                                         wih2, whh2, bih2, bhh2,
                                         wlin, blin, out);
}

// round 16
// speedup vs baseline: 2.9860x; 1.6294x over previous
#include <cuda_runtime.h>
#include <cuda_fp16.h>
#include <cstdint>

#define Hh 51
#define Lt 999
#define NB 16
#define NCTA 128
#define THREADS 512
#define WARPS 16
#define NTW 2          // n8-tiles per warp (32 tiles total)
#define NCH1 4         // k16 chunks layer1 (K=64: h1[51] + x + pad)
#define NCH2 8         // k16 chunks layer2 (two sides of 4)
#define XCHP 65
#define RSTRIDE 512    // words per region (single fp16-pair plane, 4 chunks x 128)

// shared memory u32-word offsets
#define OFF_B1PK 0
#define SZ_B1PK (32*NCH1*32*2)           // 8192 words (hi-only, uint2 per lane)
#define OFF_B2PK (OFF_B1PK + SZ_B1PK)
#define SZ_B2PK (32*NCH2*32*2)           // 16384 words
#define OFF_HBUF (OFF_B2PK + SZ_B2PK)    // 4 regions: R0,R1 (h1+x), Q0,Q1 (h2)
#define SZ_HBUF (4*RSTRIDE)              // 2048
#define OFF_OCH  (OFF_HBUF + SZ_HBUF)
#define OFF_OP   (OFF_OCH + NB*XCHP)     // 2 x 256 double-buffered partials
#define OFF_BLIN (OFF_OP + 2*WARPS*NB)
#define SMEM_FLOATS (OFF_BLIN + 4)

__device__ __forceinline__ void mma16(float* d, uint4 a, uint32_t b0, uint32_t b1) {
    asm("mma.sync.aligned.m16n8k16.row.col.f32.f16.f16.f32 "
        "{%0,%1,%2,%3}, {%4,%5,%6,%7}, {%8,%9}, {%0,%1,%2,%3};"
        : "+f"(d[0]), "+f"(d[1]), "+f"(d[2]), "+f"(d[3])
        : "r"(a.x), "r"(a.y), "r"(a.z), "r"(a.w), "r"(b0), "r"(b1));
}
__device__ __forceinline__ float tanhapx(float x) {
    float r; asm("tanh.approx.f32 %0, %1;" : "=f"(r) : "f"(x)); return r;
}
// word index for (region, batch b, unit u); u16 slot = word*2 + (u&1)
__device__ __forceinline__ int widx(int region, int b, int u) {
    const int ch = u >> 4, kin = u & 15;
    const int ln = ((b & 7) << 2) + ((kin & 7) >> 1);
    const int reg = ((kin >= 8) ? 2 : 0) + ((b >= 8) ? 1 : 0);
    return region*RSTRIDE + ch*128 + ln*4 + reg;
}
__device__ __forceinline__ void store_h(uint16_t* hb16, int region, int b, int u, float v) {
    hb16[widx(region, b, u)*2 + (u & 1)] = __half_as_ushort(__float2half_rn(v));
}
// pack two adjacent-k weights into one u32 (plain fp16, no compensation)
__device__ __forceinline__ uint32_t pack_w(float w0, float w1) {
    const uint16_t b0 = __half_as_ushort(__float2half_rn(w0));
    const uint16_t b1 = __half_as_ushort(__float2half_rn(w1));
    return ((uint32_t)b1 << 16) | b0;
}

__global__ void __launch_bounds__(THREADS, 1)
lstm_kernel(const float* __restrict__ x,
            const float* __restrict__ gWih1, const float* __restrict__ gWhh1,
            const float* __restrict__ gbih1, const float* __restrict__ gbhh1,
            const float* __restrict__ gWih2, const float* __restrict__ gWhh2,
            const float* __restrict__ gbih2, const float* __restrict__ gbhh2,
            const float* __restrict__ gWlin, const float* __restrict__ gblin,
            float* __restrict__ out)
{
    extern __shared__ float sm[];
    uint32_t* b1pk = (uint32_t*)(sm + OFF_B1PK);
    uint32_t* b2pk = (uint32_t*)(sm + OFF_B2PK);
    float* hbuf = sm + OFF_HBUF;
    uint16_t* hb16 = (uint16_t*)hbuf;
    float* och  = sm + OFF_OCH;
    float* opart= sm + OFF_OP;

    const int tid  = threadIdx.x;
    const int wid  = tid >> 5;
    const int lane = tid & 31;
    const int gid  = lane >> 2, tq = lane & 3;
    const int bmy  = gid + ((tq & 1) << 3);   // this lane's batch
    const int uh   = tq >> 1;                 // unit half within tile
    const int b0   = blockIdx.x * NB;

    // ---- pack layer-1 weights (fp16 hi-only fragment layout) ----
    // idx: reg=idx&1 (b0/b1 frag, k offset 0/8), lane, ch, tau
    for (int idx = tid; idx < SZ_B1PK; idx += THREADS) {
        const int reg = idx & 1;
        const int ln  = (idx >> 1) & 31;
        const int ch  = (idx >> 6) & (NCH1-1);
        const int tau = idx >> 8;
        const int grp = ln >> 2, tql = ln & 3;
        const int n = tau*8 + grp;
        const int u = n >> 2, ty = n & 3;
        const int kb = ch*16 + 2*tql + reg*8;
        float w[2];
        #pragma unroll
        for (int h = 0; h < 2; h++) {
            const int k = kb + h;
            float v = 0.f;
            if (u < Hh) {
                const int R = ty*Hh + u;
                if (k < Hh)       v = gWhh1[R*Hh + k];
                else if (k == Hh) v = gWih1[R];          // x slot (unit 51)
            }
            w[h] = v;
        }
        b1pk[idx] = pack_w(w[0], w[1]);
    }
    // ---- pack layer-2 weights: chunks 0-3 = Wih2 (h1 side), 4-7 = Whh2 ----
    for (int idx = tid; idx < SZ_B2PK; idx += THREADS) {
        const int reg = idx & 1;
        const int ln  = (idx >> 1) & 31;
        const int ch  = (idx >> 6) & (NCH2-1);
        const int tau = idx >> 9;
        const int grp = ln >> 2, tql = ln & 3;
        const int n = tau*8 + grp;
        const int u = n >> 2, ty = n & 3;
        const int kb = (ch & 3)*16 + 2*tql + reg*8;
        float w[2];
        #pragma unroll
        for (int h = 0; h < 2; h++) {
            const int k = kb + h;
            float v = 0.f;
            if (u < Hh && k < Hh) {
                const int R = ty*Hh + u;
                v = (ch < 4) ? gWih2[R*Hh + k] : gWhh2[R*Hh + k];
            }
            w[h] = v;
        }
        b2pk[idx] = pack_w(w[0], w[1]);
    }
    for (int i = tid; i < SZ_HBUF; i += THREADS) hbuf[i] = 0.f;
    if (tid == 0) sm[OFF_BLIN] = gblin[0];
    __syncthreads();
    // x[0] into region 1 (prologue read region)
    if (tid < NB) store_h(hb16, 1, tid, 51, x[(b0 + tid)*Lt + 0]);
    // per-lane exact biases: half-bias for i,f,o (sigmoid-via-tanh), full for g
    float wl[NTW], hb1[NTW][3], bg1[NTW], hb2[NTW][3], bg2[NTW];
    #pragma unroll
    for (int j = 0; j < NTW; j++) {
        const int u = 2*(wid + 16*j) + uh;
        const bool ok = (u < Hh);
        wl[j] = ok ? gWlin[u] : 0.f;
        hb1[j][0] = ok ? 0.5f*(gbih1[u] + gbhh1[u]) : 0.f;
        hb1[j][1] = ok ? 0.5f*(gbih1[Hh+u] + gbhh1[Hh+u]) : 0.f;
        bg1[j]    = ok ? (gbih1[2*Hh+u] + gbhh1[2*Hh+u]) : 0.f;
        hb1[j][2] = ok ? 0.5f*(gbih1[3*Hh+u] + gbhh1[3*Hh+u]) : 0.f;
        hb2[j][0] = ok ? 0.5f*(gbih2[u] + gbhh2[u]) : 0.f;
        hb2[j][1] = ok ? 0.5f*(gbih2[Hh+u] + gbhh2[Hh+u]) : 0.f;
        bg2[j]    = ok ? (gbih2[2*Hh+u] + gbhh2[2*Hh+u]) : 0.f;
        hb2[j][2] = ok ? 0.5f*(gbih2[3*Hh+u] + gbhh2[3*Hh+u]) : 0.f;
    }
    float cst1[NTW] = {0.f,0.f}, cst2[NTW] = {0.f,0.f};
    __syncthreads();

    // ---- hoist B1 (layer-1) and qr-side B2 (Whh2) fragments into registers ----
    uint2 B1R[NTW][NCH1], B2R[NTW][NCH1];
    #pragma unroll
    for (int j = 0; j < NTW; j++) {
        const int tau = wid + 16*j;
        #pragma unroll
        for (int c = 0; c < NCH1; c++) {
            B1R[j][c] = *(const uint2*)&b1pk[((tau*NCH1 + c)*32 + lane)*2];
            B2R[j][c] = *(const uint2*)&b2pk[((tau*NCH2 + 4 + c)*32 + lane)*2];
        }
    }

    // ================= prologue: h1[0] = cell1(x[0], 0) =================
    {
        float xf = 0.f;
        if (tid < NB) xf = x[(b0 + tid)*Lt + 1];
        float a1[NTW][4];
        #pragma unroll
        for (int j = 0; j < NTW; j++) { a1[j][0]=a1[j][1]=a1[j][2]=a1[j][3]=0.f; }
        #pragma unroll
        for (int c = 0; c < NCH1; c++) {
            const uint4 ah = *(const uint4*)&hbuf[1*RSTRIDE + c*128 + lane*4];
            #pragma unroll
            for (int j = 0; j < NTW; j++)
                mma16(a1[j], ah, B1R[j][c].x, B1R[j][c].y);
        }
        #pragma unroll
        for (int j = 0; j < NTW; j++) {
            const int u = 2*(wid + 16*j) + uh;
            const float sA = (tq & 1) ? a1[j][0] : a1[j][2];
            const float sB = (tq & 1) ? a1[j][1] : a1[j][3];
            const float rA = __shfl_xor_sync(0xffffffffu, sA, 1);
            const float rB = __shfl_xor_sync(0xffffffffu, sB, 1);
            float gi, gf, gg, go;
            if (tq & 1) { gi = rA; gf = rB; gg = a1[j][2]; go = a1[j][3]; }
            else        { gi = a1[j][0]; gf = a1[j][1]; gg = rA; go = rB; }
            const float si = fmaf(0.5f, tanhapx(fmaf(0.5f, gi, hb1[j][0])), 0.5f);
            const float sf = fmaf(0.5f, tanhapx(fmaf(0.5f, gf, hb1[j][1])), 0.5f);
            const float tg = tanhapx(gg + bg1[j]);
            const float cn = fmaf(sf, cst1[j], si*tg);
            cst1[j] = cn;
            const float so = fmaf(0.5f, tanhapx(fmaf(0.5f, go, hb1[j][2])), 0.5f);
            const float hn = so * tanhapx(cn);
            if (u < Hh) store_h(hb16, 0, bmy, u, hn);
        }
        if (tid < NB) store_h(hb16, 0, tid, 51, xf);
        __syncthreads();
    }

    // ================= main loop: step n does L1[n+1] + L2[n] =================
    for (int n = 0; n < Lt; ++n) {
        const int rr = n & 1, wr = 1 - rr;       // R (h1+x) regions
        const int qr = 2 + rr, qw = 3 - rr;      // Q (h2) regions

        float xf = 0.f;
        const bool havex = (tid < NB) && (n + 2 < Lt);
        if (havex) xf = x[(b0 + tid)*Lt + n + 2];

        float a1[NTW][4], a2[NTW][4];
        #pragma unroll
        for (int j = 0; j < NTW; j++) {
            a1[j][0]=a1[j][1]=a1[j][2]=a1[j][3]=0.f;
            a2[j][0]=a2[j][1]=a2[j][2]=a2[j][3]=0.f;
        }
        // ---- rr chunks (h1[n] + x[n+1]) feed BOTH layers ----
        #pragma unroll
        for (int c = 0; c < NCH1; c++) {
            const uint4 ah = *(const uint4*)&hbuf[rr*RSTRIDE + c*128 + lane*4];
            #pragma unroll
            for (int j = 0; j < NTW; j++) {
                const int tau = wid + 16*j;
                mma16(a1[j], ah, B1R[j][c].x, B1R[j][c].y);
                const uint2 b2v = *(const uint2*)&b2pk[((tau*NCH2 + c)*32 + lane)*2];
                mma16(a2[j], ah, b2v.x, b2v.y);
            }
        }

        // ---- L1 epilogue (scheduler overlaps with qr MMAs below) ----
        #pragma unroll
        for (int j = 0; j < NTW; j++) {
            const int u = 2*(wid + 16*j) + uh;
            const float sA = (tq & 1) ? a1[j][0] : a1[j][2];
            const float sB = (tq & 1) ? a1[j][1] : a1[j][3];
            const float rA = __shfl_xor_sync(0xffffffffu, sA, 1);
            const float rB = __shfl_xor_sync(0xffffffffu, sB, 1);
            float gi, gf, gg, go;
            if (tq & 1) { gi = rA; gf = rB; gg = a1[j][2]; go = a1[j][3]; }
            else        { gi = a1[j][0]; gf = a1[j][1]; gg = rA; go = rB; }
            const float si = fmaf(0.5f, tanhapx(fmaf(0.5f, gi, hb1[j][0])), 0.5f);
            const float sf = fmaf(0.5f, tanhapx(fmaf(0.5f, gf, hb1[j][1])), 0.5f);
            const float tg = tanhapx(gg + bg1[j]);
            const float cn = fmaf(sf, cst1[j], si*tg);
            cst1[j] = cn;
            const float so = fmaf(0.5f, tanhapx(fmaf(0.5f, go, hb1[j][2])), 0.5f);
            const float hn = so * tanhapx(cn);
            if (u < Hh) store_h(hb16, wr, bmy, u, hn);
        }
        if (havex) store_h(hb16, wr, tid, 51, xf);

        // ---- qr chunks (h2[n-1]) feed layer-2, B from registers ----
        #pragma unroll
        for (int c = 0; c < NCH1; c++) {
            const uint4 ah = *(const uint4*)&hbuf[qr*RSTRIDE + c*128 + lane*4];
            #pragma unroll
            for (int j = 0; j < NTW; j++)
                mma16(a2[j], ah, B2R[j][c].x, B2R[j][c].y);
        }

        // ---- L2 epilogue -> h2[n] into qw, output partial ----
        float ypart = 0.f;
        #pragma unroll
        for (int j = 0; j < NTW; j++) {
            const int u = 2*(wid + 16*j) + uh;
            const float sA = (tq & 1) ? a2[j][0] : a2[j][2];
            const float sB = (tq & 1) ? a2[j][1] : a2[j][3];
            const float rA = __shfl_xor_sync(0xffffffffu, sA, 1);
            const float rB = __shfl_xor_sync(0xffffffffu, sB, 1);
            float gi, gf, gg, go;
            if (tq & 1) { gi = rA; gf = rB; gg = a2[j][2]; go = a2[j][3]; }
            else        { gi = a2[j][0]; gf = a2[j][1]; gg = rA; go = rB; }
            const float si = fmaf(0.5f, tanhapx(fmaf(0.5f, gi, hb2[j][0])), 0.5f);
            const float sf = fmaf(0.5f, tanhapx(fmaf(0.5f, gf, hb2[j][1])), 0.5f);
            const float tg = tanhapx(gg + bg2[j]);
            const float cn = fmaf(sf, cst2[j], si*tg);
            cst2[j] = cn;
            const float so = fmaf(0.5f, tanhapx(fmaf(0.5f, go, hb2[j][2])), 0.5f);
            const float hn = so * tanhapx(cn);
            if (u < Hh) store_h(hb16, qw, bmy, u, hn);
            ypart = fmaf(hn, wl[j], ypart);
        }
        const float ys = ypart + __shfl_xor_sync(0xffffffffu, ypart, 2);
        if (tq < 2) opart[(n & 1)*(WARPS*NB) + wid*NB + ((tq & 1) << 3) + gid] = ys;
        __syncthreads();   // one barrier per step

        if (tid < NB) {
            float s = sm[OFF_BLIN];
            #pragma unroll
            for (int w8 = 0; w8 < WARPS; w8++)
                s += opart[(n & 1)*(WARPS*NB) + w8*NB + tid];
            och[tid*XCHP + (n & 63)] = s;
        }

        // ---- flush output chunk (coalesced) ----
        if ((n & 63) == 63 || n == Lt-1) {
            __syncthreads();
            const int t0c = n & ~63;
            const int wd = (n & 63) + 1;
            for (int i = tid; i < NB*wd; i += THREADS) {
                const int row = i / wd, col = i - row*wd;
                out[(b0+row)*Lt + t0c + col] = och[row*XCHP + col];
            }
        }
    }
}

extern "C" void kernel_launch(void* const* d_in, const int* in_sizes, int n_in,
                              void* d_out, int out_size)
{
    const float* x     = (const float*)d_in[0];
    const float* wih1  = (const float*)d_in[1];
    const float* whh1  = (const float*)d_in[2];
    const float* bih1  = (const float*)d_in[3];
    const float* bhh1  = (const float*)d_in[4];
    const float* wih2  = (const float*)d_in[5];
    const float* whh2  = (const float*)d_in[6];
    const float* bih2  = (const float*)d_in[7];
    const float* bhh2  = (const float*)d_in[8];
    const float* wlin  = (const float*)d_in[9];
    const float* blin  = (const float*)d_in[10];
    float* out = (float*)d_out;

    const size_t smem = (size_t)SMEM_FLOATS * sizeof(float);
    cudaFuncSetAttribute(lstm_kernel, cudaFuncAttributeMaxDynamicSharedMemorySize, (int)smem);
    lstm_kernel<<<NCTA, THREADS, smem>>>(x, wih1, whh1, bih1, bhh1,
                                         wih2, whh2, bih2, bhh2,
                                         wlin, blin, out);
}

// round 17
// speedup vs baseline: 3.0179x; 1.0107x over previous
#include <cuda_runtime.h>
#include <cuda_fp16.h>
#include <cstdint>

#define Hh 51
#define Lt 999
#define NB 16
#define NCTA 128
#define THREADS 512
#define WARPS 16
#define NTW 2          // n8-tiles per warp (32 tiles total)
#define NCH1 4         // k16 chunks layer1 (K=64: h1[51] + x + pad)
#define NCH2 8         // k16 chunks layer2 (two sides of 4)
#define XCHP 65
#define RSTRIDE 512    // f32 words per region
#define RSTRIDE16 1024 // u16 slots per region

// shared memory u32-word offsets
#define OFF_B1PK 0
#define SZ_B1PK (32*NCH1*32*2)           // 8192 words (hi-only, uint2 per lane)
#define OFF_B2PK (OFF_B1PK + SZ_B1PK)
#define SZ_B2PK (32*NCH2*32*2)           // 16384 words
#define OFF_HBUF (OFF_B2PK + SZ_B2PK)    // 4 regions: R0,R1 (h1+x), Q0,Q1 (h2)
#define SZ_HBUF (4*RSTRIDE)              // 2048
#define OFF_OCH  (OFF_HBUF + SZ_HBUF)
#define OFF_OP   (OFF_OCH + NB*XCHP)     // 2 x 256 double-buffered partials
#define OFF_BLIN (OFF_OP + 2*WARPS*NB)
#define SMEM_FLOATS (OFF_BLIN + 4)

__device__ __forceinline__ void mma16(float* d, uint4 a, uint32_t b0, uint32_t b1) {
    asm("mma.sync.aligned.m16n8k16.row.col.f32.f16.f16.f32 "
        "{%0,%1,%2,%3}, {%4,%5,%6,%7}, {%8,%9}, {%0,%1,%2,%3};"
        : "+f"(d[0]), "+f"(d[1]), "+f"(d[2]), "+f"(d[3])
        : "r"(a.x), "r"(a.y), "r"(a.z), "r"(a.w), "r"(b0), "r"(b1));
}
__device__ __forceinline__ float tanhapx(float x) {
    float r; asm("tanh.approx.f32 %0, %1;" : "=f"(r) : "f"(x)); return r;
}
// u16 slot for (batch b, unit u) within region 0 (add region*RSTRIDE16)
__device__ __forceinline__ int hoff16(int b, int u) {
    const int ch = u >> 4, kin = u & 15;
    const int ln = ((b & 7) << 2) + ((kin & 7) >> 1);
    const int reg = ((kin >= 8) ? 2 : 0) + ((b >= 8) ? 1 : 0);
    return (ch*128 + ln*4 + reg)*2 + (u & 1);
}
// pack two adjacent-k weights into one u32 (plain fp16)
__device__ __forceinline__ uint32_t pack_w(float w0, float w1) {
    const uint16_t b0 = __half_as_ushort(__float2half_rn(w0));
    const uint16_t b1 = __half_as_ushort(__float2half_rn(w1));
    return ((uint32_t)b1 << 16) | b0;
}

__global__ void __launch_bounds__(THREADS, 1)
lstm_kernel(const float* __restrict__ x,
            const float* __restrict__ gWih1, const float* __restrict__ gWhh1,
            const float* __restrict__ gbih1, const float* __restrict__ gbhh1,
            const float* __restrict__ gWih2, const float* __restrict__ gWhh2,
            const float* __restrict__ gbih2, const float* __restrict__ gbhh2,
            const float* __restrict__ gWlin, const float* __restrict__ gblin,
            float* __restrict__ out)
{
    extern __shared__ float sm[];
    uint32_t* b1pk = (uint32_t*)(sm + OFF_B1PK);
    uint32_t* b2pk = (uint32_t*)(sm + OFF_B2PK);
    float* hbuf = sm + OFF_HBUF;
    uint16_t* hb16 = (uint16_t*)hbuf;
    float* och  = sm + OFF_OCH;
    float* opart= sm + OFF_OP;

    const int tid  = threadIdx.x;
    const int wid  = tid >> 5;
    const int lane = tid & 31;
    const int gid  = lane >> 2, tq = lane & 3;
    const int bmy  = gid + ((tq & 1) << 3);   // this lane's batch
    const int uh   = tq >> 1;                 // unit half within tile
    const int b0   = blockIdx.x * NB;

    // ---- pack layer-1 weights (fp16 fragment layout) ----
    for (int idx = tid; idx < SZ_B1PK; idx += THREADS) {
        const int reg = idx & 1;
        const int ln  = (idx >> 1) & 31;
        const int ch  = (idx >> 6) & (NCH1-1);
        const int tau = idx >> 8;
        const int grp = ln >> 2, tql = ln & 3;
        const int n = tau*8 + grp;
        const int u = n >> 2, ty = n & 3;
        const int kb = ch*16 + 2*tql + reg*8;
        float w[2];
        #pragma unroll
        for (int h = 0; h < 2; h++) {
            const int k = kb + h;
            float v = 0.f;
            if (u < Hh) {
                const int R = ty*Hh + u;
                if (k < Hh)       v = gWhh1[R*Hh + k];
                else if (k == Hh) v = gWih1[R];          // x slot (unit 51)
            }
            w[h] = v;
        }
        b1pk[idx] = pack_w(w[0], w[1]);
    }
    // ---- pack layer-2 weights: chunks 0-3 = Wih2 (h1 side), 4-7 = Whh2 ----
    for (int idx = tid; idx < SZ_B2PK; idx += THREADS) {
        const int reg = idx & 1;
        const int ln  = (idx >> 1) & 31;
        const int ch  = (idx >> 6) & (NCH2-1);
        const int tau = idx >> 9;
        const int grp = ln >> 2, tql = ln & 3;
        const int n = tau*8 + grp;
        const int u = n >> 2, ty = n & 3;
        const int kb = (ch & 3)*16 + 2*tql + reg*8;
        float w[2];
        #pragma unroll
        for (int h = 0; h < 2; h++) {
            const int k = kb + h;
            float v = 0.f;
            if (u < Hh && k < Hh) {
                const int R = ty*Hh + u;
                v = (ch < 4) ? gWih2[R*Hh + k] : gWhh2[R*Hh + k];
            }
            w[h] = v;
        }
        b2pk[idx] = pack_w(w[0], w[1]);
    }
    for (int i = tid; i < SZ_HBUF; i += THREADS) hbuf[i] = 0.f;
    if (tid == 0) sm[OFF_BLIN] = gblin[0];
    __syncthreads();
    // x[0] into region 1 (prologue read region)
    const int offX = hoff16(tid < NB ? tid : 0, 51);
    if (tid < NB)
        hb16[1*RSTRIDE16 + offX] = __half_as_ushort(__float2half_rn(x[(b0 + tid)*Lt + 0]));
    // per-lane exact biases; precomputed h-store offsets
    float wl[NTW], hb1[NTW][3], bg1[NTW], hb2[NTW][3], bg2[NTW];
    int offH[NTW]; bool okU[NTW];
    #pragma unroll
    for (int j = 0; j < NTW; j++) {
        const int u = 2*(wid + 16*j) + uh;
        const bool ok = (u < Hh);
        okU[j] = ok;
        offH[j] = hoff16(bmy, ok ? u : 0);
        wl[j] = ok ? gWlin[u] : 0.f;
        hb1[j][0] = ok ? 0.5f*(gbih1[u] + gbhh1[u]) : 0.f;
        hb1[j][1] = ok ? 0.5f*(gbih1[Hh+u] + gbhh1[Hh+u]) : 0.f;
        bg1[j]    = ok ? (gbih1[2*Hh+u] + gbhh1[2*Hh+u]) : 0.f;
        hb1[j][2] = ok ? 0.5f*(gbih1[3*Hh+u] + gbhh1[3*Hh+u]) : 0.f;
        hb2[j][0] = ok ? 0.5f*(gbih2[u] + gbhh2[u]) : 0.f;
        hb2[j][1] = ok ? 0.5f*(gbih2[Hh+u] + gbhh2[Hh+u]) : 0.f;
        bg2[j]    = ok ? (gbih2[2*Hh+u] + gbhh2[2*Hh+u]) : 0.f;
        hb2[j][2] = ok ? 0.5f*(gbih2[3*Hh+u] + gbhh2[3*Hh+u]) : 0.f;
    }
    float cst1[NTW] = {0.f,0.f}, cst2[NTW] = {0.f,0.f};
    __syncthreads();

    // ---- hoist B1 (layer-1) and qr-side B2 (Whh2) fragments into registers ----
    uint2 B1R[NTW][NCH1], B2R[NTW][NCH1];
    #pragma unroll
    for (int j = 0; j < NTW; j++) {
        const int tau = wid + 16*j;
        #pragma unroll
        for (int c = 0; c < NCH1; c++) {
            B1R[j][c] = *(const uint2*)&b1pk[((tau*NCH1 + c)*32 + lane)*2];
            B2R[j][c] = *(const uint2*)&b2pk[((tau*NCH2 + 4 + c)*32 + lane)*2];
        }
    }

    // ================= prologue: h1[0] = cell1(x[0], 0) =================
    {
        float xf = 0.f;
        if (tid < NB) xf = x[(b0 + tid)*Lt + 1];
        float a1[NTW][4];
        #pragma unroll
        for (int j = 0; j < NTW; j++) { a1[j][0]=a1[j][1]=a1[j][2]=a1[j][3]=0.f; }
        #pragma unroll
        for (int c = 0; c < NCH1; c++) {
            const uint4 ah = *(const uint4*)&hbuf[1*RSTRIDE + c*128 + lane*4];
            #pragma unroll
            for (int j = 0; j < NTW; j++)
                mma16(a1[j], ah, B1R[j][c].x, B1R[j][c].y);
        }
        #pragma unroll
        for (int j = 0; j < NTW; j++) {
            const float sA = (tq & 1) ? a1[j][0] : a1[j][2];
            const float sB = (tq & 1) ? a1[j][1] : a1[j][3];
            const float rA = __shfl_xor_sync(0xffffffffu, sA, 1);
            const float rB = __shfl_xor_sync(0xffffffffu, sB, 1);
            float gi, gf, gg, go;
            if (tq & 1) { gi = rA; gf = rB; gg = a1[j][2]; go = a1[j][3]; }
            else        { gi = a1[j][0]; gf = a1[j][1]; gg = rA; go = rB; }
            const float si = fmaf(0.5f, tanhapx(fmaf(0.5f, gi, hb1[j][0])), 0.5f);
            const float sf = fmaf(0.5f, tanhapx(fmaf(0.5f, gf, hb1[j][1])), 0.5f);
            const float tg = tanhapx(gg + bg1[j]);
            const float cn = fmaf(sf, cst1[j], si*tg);
            cst1[j] = cn;
            const float so = fmaf(0.5f, tanhapx(fmaf(0.5f, go, hb1[j][2])), 0.5f);
            const float hn = so * tanhapx(cn);
            if (okU[j]) hb16[offH[j]] = __half_as_ushort(__float2half_rn(hn));
        }
        if (tid < NB) hb16[offX] = __half_as_ushort(__float2half_rn(xf));
        __syncthreads();
    }

    // ================= main loop: step n does L1[n+1] + L2[n] =================
    #pragma unroll 2
    for (int n = 0; n < Lt; ++n) {
        const int rr = n & 1, wr = 1 - rr;       // R (h1+x) regions
        const float* pRR = hbuf + rr*RSTRIDE;
        const float* pQR = hbuf + (2 + rr)*RSTRIDE;
        const int sWR = wr*RSTRIDE16;            // L1 write region (u16 base)
        const int sQW = (3 - rr)*RSTRIDE16;      // L2 write region

        float xf = 0.f;
        const bool havex = (tid < NB) && (n + 2 < Lt);
        if (havex) xf = x[(b0 + tid)*Lt + n + 2];

        float a1[NTW][4], a2[NTW][4];
        #pragma unroll
        for (int j = 0; j < NTW; j++) {
            a1[j][0]=a1[j][1]=a1[j][2]=a1[j][3]=0.f;
            a2[j][0]=a2[j][1]=a2[j][2]=a2[j][3]=0.f;
        }
        // ---- rr chunks (h1[n] + x[n+1]) feed BOTH layers ----
        #pragma unroll
        for (int c = 0; c < NCH1; c++) {
            const uint4 ah = *(const uint4*)&pRR[c*128 + lane*4];
            #pragma unroll
            for (int j = 0; j < NTW; j++) {
                const int tau = wid + 16*j;
                mma16(a1[j], ah, B1R[j][c].x, B1R[j][c].y);
                const uint2 b2v = *(const uint2*)&b2pk[((tau*NCH2 + c)*32 + lane)*2];
                mma16(a2[j], ah, b2v.x, b2v.y);
            }
        }

        // ---- L1 epilogue (scheduler overlaps with qr MMAs below) ----
        #pragma unroll
        for (int j = 0; j < NTW; j++) {
            const float sA = (tq & 1) ? a1[j][0] : a1[j][2];
            const float sB = (tq & 1) ? a1[j][1] : a1[j][3];
            const float rA = __shfl_xor_sync(0xffffffffu, sA, 1);
            const float rB = __shfl_xor_sync(0xffffffffu, sB, 1);
            float gi, gf, gg, go;
            if (tq & 1) { gi = rA; gf = rB; gg = a1[j][2]; go = a1[j][3]; }
            else        { gi = a1[j][0]; gf = a1[j][1]; gg = rA; go = rB; }
            const float si = fmaf(0.5f, tanhapx(fmaf(0.5f, gi, hb1[j][0])), 0.5f);
            const float sf = fmaf(0.5f, tanhapx(fmaf(0.5f, gf, hb1[j][1])), 0.5f);
            const float tg = tanhapx(gg + bg1[j]);
            const float cn = fmaf(sf, cst1[j], si*tg);
            cst1[j] = cn;
            const float so = fmaf(0.5f, tanhapx(fmaf(0.5f, go, hb1[j][2])), 0.5f);
            const float hn = so * tanhapx(cn);
            if (okU[j]) hb16[sWR + offH[j]] = __half_as_ushort(__float2half_rn(hn));
        }
        if (havex) hb16[sWR + offX] = __half_as_ushort(__float2half_rn(xf));

        // ---- qr chunks (h2[n-1]) feed layer-2, B from registers ----
        #pragma unroll
        for (int c = 0; c < NCH1; c++) {
            const uint4 ah = *(const uint4*)&pQR[c*128 + lane*4];
            #pragma unroll
            for (int j = 0; j < NTW; j++)
                mma16(a2[j], ah, B2R[j][c].x, B2R[j][c].y);
        }

        // ---- L2 epilogue -> h2[n], output partial ----
        float ypart = 0.f;
        #pragma unroll
        for (int j = 0; j < NTW; j++) {
            const float sA = (tq & 1) ? a2[j][0] : a2[j][2];
            const float sB = (tq & 1) ? a2[j][1] : a2[j][3];
            const float rA = __shfl_xor_sync(0xffffffffu, sA, 1);
            const float rB = __shfl_xor_sync(0xffffffffu, sB, 1);
            float gi, gf, gg, go;
            if (tq & 1) { gi = rA; gf = rB; gg = a2[j][2]; go = a2[j][3]; }
            else        { gi = a2[j][0]; gf = a2[j][1]; gg = rA; go = rB; }
            const float si = fmaf(0.5f, tanhapx(fmaf(0.5f, gi, hb2[j][0])), 0.5f);
            const float sf = fmaf(0.5f, tanhapx(fmaf(0.5f, gf, hb2[j][1])), 0.5f);
            const float tg = tanhapx(gg + bg2[j]);
            const float cn = fmaf(sf, cst2[j], si*tg);
            cst2[j] = cn;
            const float so = fmaf(0.5f, tanhapx(fmaf(0.5f, go, hb2[j][2])), 0.5f);
            const float hn = so * tanhapx(cn);
            if (okU[j]) hb16[sQW + offH[j]] = __half_as_ushort(__float2half_rn(hn));
            ypart = fmaf(hn, wl[j], ypart);
        }
        const float ys = ypart + __shfl_xor_sync(0xffffffffu, ypart, 2);
        if (tq < 2) opart[rr*(WARPS*NB) + wid*NB + ((tq & 1) << 3) + gid] = ys;
        __syncthreads();   // one barrier per step

        if (tid < NB) {
            float s = sm[OFF_BLIN];
            #pragma unroll
            for (int w8 = 0; w8 < WARPS; w8++)
                s += opart[rr*(WARPS*NB) + w8*NB + tid];
            och[tid*XCHP + (n & 63)] = s;
        }

        // ---- flush output chunk (coalesced) ----
        if ((n & 63) == 63 || n == Lt-1) {
            __syncthreads();
            const int t0c = n & ~63;
            const int wd = (n & 63) + 1;
            for (int i = tid; i < NB*wd; i += THREADS) {
                const int row = i / wd, col = i - row*wd;
                out[(b0+row)*Lt + t0c + col] = och[row*XCHP + col];
            }
        }
    }
}

extern "C" void kernel_launch(void* const* d_in, const int* in_sizes, int n_in,
                              void* d_out, int out_size)
{
    const float* x     = (const float*)d_in[0];
    const float* wih1  = (const float*)d_in[1];
    const float* whh1  = (const float*)d_in[2];
    const float* bih1  = (const float*)d_in[3];
    const float* bhh1  = (const float*)d_in[4];
    const float* wih2  = (const float*)d_in[5];
    const float* whh2  = (const float*)d_in[6];
    const float* bih2  = (const float*)d_in[7];
    const float* bhh2  = (const float*)d_in[8];
    const float* wlin  = (const float*)d_in[9];
    const float* blin  = (const float*)d_in[10];
    float* out = (float*)d_out;

    const size_t smem = (size_t)SMEM_FLOATS * sizeof(float);
    cudaFuncSetAttribute(lstm_kernel, cudaFuncAttributeMaxDynamicSharedMemorySize, (int)smem);
    lstm_kernel<<<NCTA, THREADS, smem>>>(x, wih1, whh1, bih1, bhh1,
                                         wih2, whh2, bih2, bhh2,
                                         wlin, blin, out);
}